// round 7
// baseline (speedup 1.0000x reference)
#include <cuda_runtime.h>
#include <cuda_bf16.h>
#include <cstdint>

#define BATCH 16
#define NPTS  2048
#define KNN   16
#define NPT   (BATCH*NPTS)

// ----------------------------- scratch ------------------------------------
__device__ __align__(16) int      g_idx[NPT*KNN];
__device__ __align__(16) float    g_t64a[NPT*64];
__device__ __align__(16) float    g_t64b[NPT*64];
__device__ __align__(16) float    g_h64a[NPT*64];
__device__ __align__(16) float    g_pool64[NPT*64];
__device__ __align__(16) float    g_h128a[NPT*128];
__device__ __align__(16) float    g_pool128[NPT*128];
__device__ __align__(16) float    g_Wp1[128*64];   // (Wc1@Wlin1)[o][c]
__device__ __align__(16) float    g_bp1[128];
__device__ __align__(16) float    g_Wp2[1024*128]; // (Wc2@Wlin2)[o][c]
__device__ __align__(16) float    g_bp2[1024];
__device__ __align__(16) unsigned g_gmax[BATCH*1024];

__device__ __forceinline__ unsigned fenc(float f) {
    unsigned b = __float_as_uint(f);
    return (b & 0x80000000u) ? ~b : (b | 0x80000000u);
}
__device__ __forceinline__ float fdec(unsigned u) {
    return __uint_as_float((u & 0x80000000u) ? (u ^ 0x80000000u) : ~u);
}
__device__ __forceinline__ float neg_inf() { return __uint_as_float(0xff800000u); }

// packed f32x2 helpers (sm_100a+; ptxas never auto-fuses these)
#define MUL2(out, a, b)    asm("mul.rn.f32x2 %0, %1, %2;"     : "=l"(out) : "l"(a), "l"(b))
#define FMA2(out, a, b, c) asm("fma.rn.f32x2 %0, %1, %2, %3;" : "=l"(out) : "l"(a), "l"(b), "l"(c))

__device__ __forceinline__ unsigned long long pack2(float lo, float hi) {
    unsigned long long r;
    asm("mov.b64 %0, {%1, %2};" : "=l"(r) : "f"(lo), "f"(hi));
    return r;
}
__device__ __forceinline__ void unpack2(unsigned long long v, float& lo, float& hi) {
    asm("mov.b64 {%0, %1}, %2;" : "=f"(lo), "=f"(hi) : "l"(v));
}

// ----------------------------- K: zero gmax --------------------------------
__global__ void zero_gmax_kernel() {
    g_gmax[blockIdx.x * 1024 + threadIdx.x] = 0u;
}

// ------------------- K: precompute W' = Wc1 @ Wlin1 ------------------------
__global__ __launch_bounds__(256) void prep_wp1_kernel(
    const float* __restrict__ Wc1, const float* __restrict__ Wlin1,
    const float* __restrict__ b_lin1, const float* __restrict__ b_c1) {
    int g = blockIdx.x * 256 + threadIdx.x;          // 8192
    int o = g >> 6, c = g & 63;
    float acc = 0.f;
    for (int m = 0; m < 64; m++) acc = fmaf(Wc1[o*64+m], Wlin1[m*64+c], acc);
    g_Wp1[o*64 + c] = acc;
    if (c == 0) {
        float bb = b_c1[o];
        for (int m = 0; m < 64; m++) bb = fmaf(Wc1[o*64+m], b_lin1[m], bb);
        g_bp1[o] = bb;
    }
}

// ------------------- K: precompute W'' = Wc2 @ Wlin2 -----------------------
__global__ __launch_bounds__(128) void prep_wp2_kernel(
    const float* __restrict__ Wc2, const float* __restrict__ Wlin2,
    const float* __restrict__ b_lin2, const float* __restrict__ b_c2) {
    int o = blockIdx.x, c = threadIdx.x;
    float acc = 0.f;
    for (int m = 0; m < 128; m++) acc = fmaf(Wc2[o*128+m], Wlin2[m*128+c], acc);
    g_Wp2[o*128 + c] = acc;
    if (c == 0) {
        float bb = b_c2[o];
        for (int m = 0; m < 128; m++) bb = fmaf(Wc2[o*128+m], b_lin2[m], bb);
        g_bp2[o] = bb;
    }
}

// ----------------------------- K: kNN (f32x2 packed) -----------------------
// One thread per query. SoA float4 candidate arrays in shared; 4 candidates
// per iteration via two f32x2 lanes; one threshold compare per 4 candidates.
// Arithmetic is bitwise-identical to the scalar version:
//   t  = fmaf(qz,sz, fmaf(qy,sy, qx*sx))
//   d  = (2t - qxx) - sxx        [2t exact => fma(2,t,-qxx) == (2t)-qxx]
__global__ __launch_bounds__(128) void knn_kernel(const float* __restrict__ pts) {
    __shared__ __align__(16) float sx[NPTS], sy[NPTS], sz[NPTS], snxx[NPTS];
    int b = blockIdx.y;
    const float* p = pts + (size_t)b * NPTS * 3;
    for (int i = threadIdx.x; i < NPTS; i += 128) {
        float x = p[i*3+0], y = p[i*3+1], z = p[i*3+2];
        sx[i] = x; sy[i] = y; sz[i] = z;
        snxx[i] = -fmaf(z, z, fmaf(y, y, x * x));
    }
    __syncthreads();
    int q = blockIdx.x * 128 + threadIdx.x;
    float qx = sx[q], qy = sy[q], qz = sz[q];
    float qxx = fmaf(qz, qz, fmaf(qy, qy, qx * qx));
    unsigned long long qx2 = pack2(qx, qx), qy2 = pack2(qy, qy), qz2 = pack2(qz, qz);
    unsigned long long nqxx2 = pack2(-qxx, -qxx);
    unsigned long long two2 = pack2(2.0f, 2.0f);

    float vals[KNN]; int idxs[KNN];
    #pragma unroll
    for (int s = 0; s < KNN; s++) { vals[s] = neg_inf(); idxs[s] = 0; }

    const ulonglong2* X4 = (const ulonglong2*)sx;
    const ulonglong2* Y4 = (const ulonglong2*)sy;
    const ulonglong2* Z4 = (const ulonglong2*)sz;
    const ulonglong2* C4 = (const ulonglong2*)snxx;

    #pragma unroll 2
    for (int c4 = 0; c4 < NPTS/4; c4++) {
        ulonglong2 X = X4[c4], Y = Y4[c4], Z = Z4[c4], C = C4[c4];
        unsigned long long t0, t1, d0p, d1p;
        MUL2(t0, qx2, X.x);  MUL2(t1, qx2, X.y);
        FMA2(t0, qy2, Y.x, t0);  FMA2(t1, qy2, Y.y, t1);
        FMA2(t0, qz2, Z.x, t0);  FMA2(t1, qz2, Z.y, t1);
        FMA2(t0, two2, t0, nqxx2);  FMA2(t1, two2, t1, nqxx2);  // (2t)-qxx exactly
        // d = (2t-qxx) + (-sxx)
        asm("add.rn.f32x2 %0, %1, %2;" : "=l"(d0p) : "l"(t0), "l"(C.x));
        asm("add.rn.f32x2 %0, %1, %2;" : "=l"(d1p) : "l"(t1), "l"(C.y));
        float d0, d1, d2, d3;
        unpack2(d0p, d0, d1);
        unpack2(d1p, d2, d3);
        float m = fmaxf(fmaxf(d0, d1), fmaxf(d2, d3));
        if (m > vals[KNN-1]) {
            int jb = c4 * 4;
            float dd[4] = {d0, d1, d2, d3};
            #pragma unroll
            for (int u = 0; u < 4; u++) {
                float d = dd[u];
                if (d > vals[KNN-1]) {
                    vals[KNN-1] = d; idxs[KNN-1] = jb + u;
                    #pragma unroll
                    for (int s = KNN-1; s > 0; s--) {
                        if (vals[s] > vals[s-1]) {
                            float tv = vals[s]; vals[s] = vals[s-1]; vals[s-1] = tv;
                            int   ti = idxs[s]; idxs[s] = idxs[s-1]; idxs[s-1] = ti;
                        } else break;
                    }
                }
            }
        }
    }
    int* o = g_idx + ((size_t)b * NPTS + q) * KNN;
    #pragma unroll
    for (int s = 0; s < KNN; s++) o[s] = idxs[s];
}

// --------------- K: local_cov + mlp1 layer a (12->64 relu) -----------------
__global__ __launch_bounds__(256) void cov_l1_kernel(
    const float* __restrict__ pts,
    const float* __restrict__ W1, const float* __restrict__ b1) {
    __shared__ float sW[12*64];   // [c][o]
    __shared__ float sb[64];
    int tid = threadIdx.x;
    for (int i = tid; i < 64*12; i += 256) { int o = i / 12, c = i % 12; sW[c*64 + o] = W1[i]; }
    if (tid < 64) sb[tid] = b1[tid];
    __syncthreads();
    int w = tid >> 5, lane = tid & 31;
    int gid = blockIdx.x * 8 + w;
    int b = gid >> 11, n = gid & 2047;
    const float* p = pts + (size_t)b * NPTS * 3;
    const int* id = g_idx + (size_t)gid * KNN;
    int i0 = id[0], i1 = id[1];
    float f[12];
    f[0] = p[n*3+0]; f[1] = p[n*3+1]; f[2] = p[n*3+2];
    float a0 = p[i0*3+0], a1 = p[i0*3+1], a2 = p[i0*3+2];
    float c0 = p[i1*3+0], c1 = p[i1*3+1], c2 = p[i1*3+2];
    f[3] = a0*c0; f[4]  = a0*c1; f[5]  = a0*c2;
    f[6] = a1*c0; f[7]  = a1*c1; f[8]  = a1*c2;
    f[9] = a2*c0; f[10] = a2*c1; f[11] = a2*c2;
    float h0 = sb[lane], h1 = sb[lane+32];
    #pragma unroll
    for (int c = 0; c < 12; c++) {
        h0 = fmaf(sW[c*64 + lane],      f[c], h0);
        h1 = fmaf(sW[c*64 + lane + 32], f[c], h1);
    }
    g_t64a[(size_t)gid*64 + lane]      = fmaxf(h0, 0.f);
    g_t64a[(size_t)gid*64 + lane + 32] = fmaxf(h1, 0.f);
}

// ----------------- K: register-tiled GEMM + bias + relu --------------------
template<int K, int TILE_O>
__global__ __launch_bounds__(256) void gemm_bias_relu_kernel(
    const float* __restrict__ A, const float* __restrict__ B,
    const float* __restrict__ bias, float* __restrict__ C, int O_total) {
    constexpr int TN = 128, KC = 16, PAD = 4;
    constexpr int TO = TILE_O / 16;
    __shared__ float sA[KC][TN + PAD];
    __shared__ float sB[KC][TILE_O + PAD];
    int tid = threadIdx.x;
    int n0 = blockIdx.x * TN;
    int o0 = blockIdx.y * TILE_O;
    int nsub = tid >> 4, osub = tid & 15;
    float acc[8][TO];
    #pragma unroll
    for (int i = 0; i < 8; i++)
        #pragma unroll
        for (int j = 0; j < TO; j++) acc[i][j] = 0.f;

    float breg[TO];
    #pragma unroll
    for (int j = 0; j < TO; j++) breg[j] = bias[o0 + osub*TO + j];

    for (int k0 = 0; k0 < K; k0 += KC) {
        __syncthreads();
        {
            int n_l = tid >> 1, k_l = (tid & 1) * 8;
            const float4* p = (const float4*)(A + (size_t)(n0 + n_l) * K + k0 + k_l);
            float4 v0 = p[0], v1 = p[1];
            sA[k_l+0][n_l] = v0.x; sA[k_l+1][n_l] = v0.y;
            sA[k_l+2][n_l] = v0.z; sA[k_l+3][n_l] = v0.w;
            sA[k_l+4][n_l] = v1.x; sA[k_l+5][n_l] = v1.y;
            sA[k_l+6][n_l] = v1.z; sA[k_l+7][n_l] = v1.w;
        }
        if constexpr (TILE_O == 128) {
            int o_l = tid >> 1, k_l = (tid & 1) * 8;
            const float4* p = (const float4*)(B + (size_t)(o0 + o_l) * K + k0 + k_l);
            float4 v0 = p[0], v1 = p[1];
            sB[k_l+0][o_l] = v0.x; sB[k_l+1][o_l] = v0.y;
            sB[k_l+2][o_l] = v0.z; sB[k_l+3][o_l] = v0.w;
            sB[k_l+4][o_l] = v1.x; sB[k_l+5][o_l] = v1.y;
            sB[k_l+6][o_l] = v1.z; sB[k_l+7][o_l] = v1.w;
        } else {
            int o_l = tid >> 2, k_l = (tid & 3) * 4;
            float4 v = *(const float4*)(B + (size_t)(o0 + o_l) * K + k0 + k_l);
            sB[k_l+0][o_l] = v.x; sB[k_l+1][o_l] = v.y;
            sB[k_l+2][o_l] = v.z; sB[k_l+3][o_l] = v.w;
        }
        __syncthreads();
        #pragma unroll
        for (int kk = 0; kk < KC; kk++) {
            float4 a0 = *(const float4*)&sA[kk][nsub*8];
            float4 a1 = *(const float4*)&sA[kk][nsub*8+4];
            float af[8] = {a0.x,a0.y,a0.z,a0.w,a1.x,a1.y,a1.z,a1.w};
            float bf[TO];
            if constexpr (TO == 8) {
                float4 b0 = *(const float4*)&sB[kk][osub*8];
                float4 b1 = *(const float4*)&sB[kk][osub*8+4];
                bf[0]=b0.x; bf[1]=b0.y; bf[2]=b0.z; bf[3]=b0.w;
                bf[4]=b1.x; bf[5]=b1.y; bf[6]=b1.z; bf[7]=b1.w;
            } else {
                float4 b0 = *(const float4*)&sB[kk][osub*4];
                bf[0]=b0.x; bf[1]=b0.y; bf[2]=b0.z; bf[3]=b0.w;
            }
            #pragma unroll
            for (int i = 0; i < 8; i++)
                #pragma unroll
                for (int j = 0; j < TO; j++)
                    acc[i][j] = fmaf(af[i], bf[j], acc[i][j]);
        }
    }
    #pragma unroll
    for (int i = 0; i < 8; i++) {
        size_t base = (size_t)(n0 + nsub*8 + i) * O_total + o0 + osub*TO;
        #pragma unroll
        for (int j = 0; j < TO; j += 4) {
            float4 v;
            v.x = fmaxf(acc[i][j+0] + breg[j+0], 0.f);
            v.y = fmaxf(acc[i][j+1] + breg[j+1], 0.f);
            v.z = fmaxf(acc[i][j+2] + breg[j+2], 0.f);
            v.w = fmaxf(acc[i][j+3] + breg[j+3], 0.f);
            *(float4*)(C + base + j) = v;
        }
    }
}

// --------- K: big GEMM (pool128 x W''^T), fused per-batch max --------------
__global__ __launch_bounds__(256) void gemm_max_kernel(
    const float* __restrict__ A, const float* __restrict__ B) {
    constexpr int TN = 128, KC = 16, PAD = 4, K = 128, TILE_O = 128;
    __shared__ float sA[KC][TN + PAD];
    __shared__ float sB[KC][TILE_O + PAD];
    int tid = threadIdx.x;
    int n0 = blockIdx.x * TN;
    int o0 = blockIdx.y * TILE_O;
    int nsub = tid >> 4, osub = tid & 15;
    float acc[8][8];
    #pragma unroll
    for (int i = 0; i < 8; i++)
        #pragma unroll
        for (int j = 0; j < 8; j++) acc[i][j] = 0.f;

    for (int k0 = 0; k0 < K; k0 += KC) {
        __syncthreads();
        {
            int n_l = tid >> 1, k_l = (tid & 1) * 8;
            const float4* p = (const float4*)(A + (size_t)(n0 + n_l) * K + k0 + k_l);
            float4 v0 = p[0], v1 = p[1];
            sA[k_l+0][n_l] = v0.x; sA[k_l+1][n_l] = v0.y;
            sA[k_l+2][n_l] = v0.z; sA[k_l+3][n_l] = v0.w;
            sA[k_l+4][n_l] = v1.x; sA[k_l+5][n_l] = v1.y;
            sA[k_l+6][n_l] = v1.z; sA[k_l+7][n_l] = v1.w;
        }
        {
            int o_l = tid >> 1, k_l = (tid & 1) * 8;
            const float4* p = (const float4*)(B + (size_t)(o0 + o_l) * K + k0 + k_l);
            float4 v0 = p[0], v1 = p[1];
            sB[k_l+0][o_l] = v0.x; sB[k_l+1][o_l] = v0.y;
            sB[k_l+2][o_l] = v0.z; sB[k_l+3][o_l] = v0.w;
            sB[k_l+4][o_l] = v1.x; sB[k_l+5][o_l] = v1.y;
            sB[k_l+6][o_l] = v1.z; sB[k_l+7][o_l] = v1.w;
        }
        __syncthreads();
        #pragma unroll
        for (int kk = 0; kk < KC; kk++) {
            float4 a0 = *(const float4*)&sA[kk][nsub*8];
            float4 a1 = *(const float4*)&sA[kk][nsub*8+4];
            float4 b0 = *(const float4*)&sB[kk][osub*8];
            float4 b1 = *(const float4*)&sB[kk][osub*8+4];
            float af[8] = {a0.x,a0.y,a0.z,a0.w,a1.x,a1.y,a1.z,a1.w};
            float bf[8] = {b0.x,b0.y,b0.z,b0.w,b1.x,b1.y,b1.z,b1.w};
            #pragma unroll
            for (int i = 0; i < 8; i++)
                #pragma unroll
                for (int j = 0; j < 8; j++)
                    acc[i][j] = fmaf(af[i], bf[j], acc[i][j]);
        }
    }
    float m[8];
    #pragma unroll
    for (int j = 0; j < 8; j++) {
        float mm = acc[0][j];
        #pragma unroll
        for (int i = 1; i < 8; i++) mm = fmaxf(mm, acc[i][j]);
        m[j] = mm;
    }
    __syncthreads();
    #pragma unroll
    for (int j = 0; j < 8; j++) sA[nsub][osub*8 + j] = m[j];
    __syncthreads();
    if (tid < 128) {
        float mm = neg_inf();
        #pragma unroll
        for (int r = 0; r < 16; r++) mm = fmaxf(mm, sA[r][tid]);
        int b = blockIdx.x >> 4;
        atomicMax(&g_gmax[b*1024 + o0 + tid], fenc(mm));
    }
}

// ----------------------------- K: pool 64 ----------------------------------
__global__ __launch_bounds__(256) void pool64_kernel() {
    int tid = threadIdx.x, w = tid >> 5, lane = tid & 31;
    int gid = blockIdx.x * 8 + w;
    int boff = (gid >> 11) << 11;
    const int* id = g_idx + (size_t)gid * KNN;
    int myid = (lane < KNN) ? id[lane] : 0;
    float m0 = neg_inf(), m1 = neg_inf();
    #pragma unroll
    for (int j = 0; j < KNN; j++) {
        int nb = __shfl_sync(0xffffffffu, myid, j);
        const float* f = g_h64a + (size_t)(boff + nb) * 64;
        m0 = fmaxf(m0, f[lane]);
        m1 = fmaxf(m1, f[lane + 32]);
    }
    g_pool64[(size_t)gid*64 + lane]      = m0;
    g_pool64[(size_t)gid*64 + lane + 32] = m1;
}

// ----------------------------- K: pool 128 ---------------------------------
__global__ __launch_bounds__(256) void pool128_kernel() {
    int tid = threadIdx.x, w = tid >> 5, lane = tid & 31;
    int gid = blockIdx.x * 8 + w;
    int boff = (gid >> 11) << 11;
    const int* id = g_idx + (size_t)gid * KNN;
    int myid = (lane < KNN) ? id[lane] : 0;
    float m0 = neg_inf(), m1 = neg_inf(), m2 = neg_inf(), m3 = neg_inf();
    #pragma unroll
    for (int j = 0; j < KNN; j++) {
        int nb = __shfl_sync(0xffffffffu, myid, j);
        const float* f = g_h128a + (size_t)(boff + nb) * 128;
        m0 = fmaxf(m0, f[lane]);
        m1 = fmaxf(m1, f[lane + 32]);
        m2 = fmaxf(m2, f[lane + 64]);
        m3 = fmaxf(m3, f[lane + 96]);
    }
    float* o = g_pool128 + (size_t)gid*128;
    o[lane] = m0; o[lane+32] = m1; o[lane+64] = m2; o[lane+96] = m3;
}

// ----------------------------- K: head MLP ---------------------------------
__global__ __launch_bounds__(512) void head_kernel(
    const float* __restrict__ W_m2a, const float* __restrict__ b_m2a,
    const float* __restrict__ W_m2b, const float* __restrict__ b_m2b,
    const float* __restrict__ W_emb, float* __restrict__ out) {
    __shared__ float sv[1024], sh1[512], sh2[512];
    int b = blockIdx.x, tid = threadIdx.x, w = tid >> 5, lane = tid & 31;
    sv[tid]       = fdec(g_gmax[b*1024 + tid])       + g_bp2[tid];
    sv[tid + 512] = fdec(g_gmax[b*1024 + tid + 512]) + g_bp2[tid + 512];
    __syncthreads();
    for (int r = 0; r < 32; r++) {
        int o = w * 32 + r;
        const float* Wr = W_m2a + (size_t)o * 1024;
        float acc = 0.f;
        #pragma unroll 8
        for (int i = 0; i < 32; i++) acc = fmaf(Wr[lane + 32*i], sv[lane + 32*i], acc);
        #pragma unroll
        for (int s = 16; s > 0; s >>= 1) acc += __shfl_xor_sync(0xffffffffu, acc, s);
        if (lane == 0) sh1[o] = fmaxf(acc + b_m2a[o], 0.f);
    }
    __syncthreads();
    for (int r = 0; r < 32; r++) {
        int o = w * 32 + r;
        const float* Wr = W_m2b + (size_t)o * 512;
        float acc = 0.f;
        #pragma unroll 8
        for (int i = 0; i < 16; i++) acc = fmaf(Wr[lane + 32*i], sh1[lane + 32*i], acc);
        #pragma unroll
        for (int s = 16; s > 0; s >>= 1) acc += __shfl_xor_sync(0xffffffffu, acc, s);
        if (lane == 0) sh2[o] = acc + b_m2b[o];
    }
    __syncthreads();
    for (int r = 0; r < 8; r++) {
        int j = w * 8 + r;
        const float* Wr = W_emb + (size_t)j * 512;
        float acc = 0.f;
        #pragma unroll 8
        for (int i = 0; i < 16; i++) acc = fmaf(Wr[lane + 32*i], sh2[lane + 32*i], acc);
        #pragma unroll
        for (int s = 16; s > 0; s >>= 1) acc += __shfl_xor_sync(0xffffffffu, acc, s);
        if (lane == 0) out[b*128 + j] = acc;
    }
}

// ----------------------------- launch --------------------------------------
extern "C" void kernel_launch(void* const* d_in, const int* in_sizes, int n_in,
                              void* d_out, int out_size) {
    const float* pts    = (const float*)d_in[0];
    const float* W_m1a  = (const float*)d_in[1];
    const float* b_m1a  = (const float*)d_in[2];
    const float* W_m1b  = (const float*)d_in[3];
    const float* b_m1b  = (const float*)d_in[4];
    const float* W_m1c  = (const float*)d_in[5];
    const float* b_m1c  = (const float*)d_in[6];
    const float* W_lin1 = (const float*)d_in[7];
    const float* b_lin1 = (const float*)d_in[8];
    const float* W_c1   = (const float*)d_in[9];
    const float* b_c1   = (const float*)d_in[10];
    const float* W_lin2 = (const float*)d_in[11];
    const float* b_lin2 = (const float*)d_in[12];
    const float* W_c2   = (const float*)d_in[13];
    const float* b_c2   = (const float*)d_in[14];
    const float* W_m2a  = (const float*)d_in[15];
    const float* b_m2a  = (const float*)d_in[16];
    const float* W_m2b  = (const float*)d_in[17];
    const float* b_m2b  = (const float*)d_in[18];
    const float* W_emb  = (const float*)d_in[19];
    float* out = (float*)d_out;

    float* t64a; cudaGetSymbolAddress((void**)&t64a, g_t64a);
    float* t64b; cudaGetSymbolAddress((void**)&t64b, g_t64b);
    float* h64a; cudaGetSymbolAddress((void**)&h64a, g_h64a);
    float* p64;  cudaGetSymbolAddress((void**)&p64,  g_pool64);
    float* h128; cudaGetSymbolAddress((void**)&h128, g_h128a);
    float* p128; cudaGetSymbolAddress((void**)&p128, g_pool128);
    float* wp1;  cudaGetSymbolAddress((void**)&wp1,  g_Wp1);
    float* bp1;  cudaGetSymbolAddress((void**)&bp1,  g_bp1);
    float* wp2;  cudaGetSymbolAddress((void**)&wp2,  g_Wp2);

    zero_gmax_kernel<<<BATCH, 1024>>>();
    prep_wp1_kernel<<<32, 256>>>(W_c1, W_lin1, b_lin1, b_c1);
    prep_wp2_kernel<<<1024, 128>>>(W_c2, W_lin2, b_lin2, b_c2);

    knn_kernel<<<dim3(NPTS/128, BATCH), 128>>>(pts);
    cov_l1_kernel<<<NPT/8, 256>>>(pts, W_m1a, b_m1a);

    gemm_bias_relu_kernel<64, 64><<<dim3(NPT/128, 1), 256>>>(t64a, W_m1b, b_m1b, t64b, 64);
    gemm_bias_relu_kernel<64, 64><<<dim3(NPT/128, 1), 256>>>(t64b, W_m1c, b_m1c, h64a, 64);

    pool64_kernel<<<NPT/8, 256>>>();
    gemm_bias_relu_kernel<64, 128><<<dim3(NPT/128, 1), 256>>>(p64, wp1, bp1, h128, 128);

    pool128_kernel<<<NPT/8, 256>>>();
    gemm_max_kernel<<<dim3(NPT/128, 8), 256>>>(p128, wp2);

    head_kernel<<<BATCH, 512>>>(W_m2a, b_m2a, W_m2b, b_m2b, W_emb, out);
}

// round 9
// speedup vs baseline: 1.6389x; 1.6389x over previous
#include <cuda_runtime.h>
#include <cuda_bf16.h>
#include <cstdint>

#define BATCH 16
#define NPTS  2048
#define KNN   16
#define NPT   (BATCH*NPTS)

// ----------------------------- scratch ------------------------------------
__device__ __align__(16) int      g_idx[NPT*KNN];
__device__ __align__(16) float    g_t64a[NPT*64];
__device__ __align__(16) float    g_t64b[NPT*64];
__device__ __align__(16) float    g_h64a[NPT*64];
__device__ __align__(16) float    g_pool64[NPT*64];
__device__ __align__(16) float    g_h128a[NPT*128];
__device__ __align__(16) float    g_pool128[NPT*128];
__device__ __align__(16) float    g_Wp1[128*64];   // (Wc1@Wlin1)[o][c]
__device__ __align__(16) float    g_bp1[128];
__device__ __align__(16) float    g_Wp2[1024*128]; // (Wc2@Wlin2)[o][c]
__device__ __align__(16) float    g_bp2[1024];
__device__ __align__(16) unsigned g_gmax[BATCH*1024];

__device__ __forceinline__ unsigned fenc(float f) {
    unsigned b = __float_as_uint(f);
    return (b & 0x80000000u) ? ~b : (b | 0x80000000u);
}
__device__ __forceinline__ float fdec(unsigned u) {
    return __uint_as_float((u & 0x80000000u) ? (u ^ 0x80000000u) : ~u);
}
__device__ __forceinline__ float neg_inf() { return __uint_as_float(0xff800000u); }

// ----------------------------- K: zero gmax --------------------------------
__global__ void zero_gmax_kernel() {
    g_gmax[blockIdx.x * 1024 + threadIdx.x] = 0u;
}

// ------------------- K: precompute W' = Wc1 @ Wlin1 ------------------------
__global__ __launch_bounds__(256) void prep_wp1_kernel(
    const float* __restrict__ Wc1, const float* __restrict__ Wlin1,
    const float* __restrict__ b_lin1, const float* __restrict__ b_c1) {
    int g = blockIdx.x * 256 + threadIdx.x;          // 8192
    int o = g >> 6, c = g & 63;
    float acc = 0.f;
    for (int m = 0; m < 64; m++) acc = fmaf(Wc1[o*64+m], Wlin1[m*64+c], acc);
    g_Wp1[o*64 + c] = acc;
    if (c == 0) {
        float bb = b_c1[o];
        for (int m = 0; m < 64; m++) bb = fmaf(Wc1[o*64+m], b_lin1[m], bb);
        g_bp1[o] = bb;
    }
}

// ------------------- K: precompute W'' = Wc2 @ Wlin2 -----------------------
__global__ __launch_bounds__(128) void prep_wp2_kernel(
    const float* __restrict__ Wc2, const float* __restrict__ Wlin2,
    const float* __restrict__ b_lin2, const float* __restrict__ b_c2) {
    int o = blockIdx.x, c = threadIdx.x;
    float acc = 0.f;
    for (int m = 0; m < 128; m++) acc = fmaf(Wc2[o*128+m], Wlin2[m*128+c], acc);
    g_Wp2[o*128 + c] = acc;
    if (c == 0) {
        float bb = b_c2[o];
        for (int m = 0; m < 128; m++) bb = fmaf(Wc2[o*128+m], b_lin2[m], bb);
        g_bp2[o] = bb;
    }
}

// ----------------------------- K: kNN (scalar, AoS float4) -----------------
// One thread per query. Shared candidates packed as float4 {x, y, z, -0.5*|p|^2}.
// Rank by r = qx*x + qy*y + qz*z - 0.5*|p|^2  (d = 2r - qxx is monotone in r
// for a fixed query, so top-k by r == top-k by neg squared distance).
// Per candidate: 1 LDS.128 + 3 FMA; one branch per 4 candidates via max-tree.
__global__ __launch_bounds__(128) void knn_kernel(const float* __restrict__ pts) {
    __shared__ __align__(16) float4 pc[NPTS];   // 32 KB
    int b = blockIdx.y;
    const float* p = pts + (size_t)b * NPTS * 3;
    for (int i = threadIdx.x; i < NPTS; i += 128) {
        float x = p[i*3+0], y = p[i*3+1], z = p[i*3+2];
        float h = -0.5f * fmaf(z, z, fmaf(y, y, x * x));
        pc[i] = make_float4(x, y, z, h);
    }
    __syncthreads();
    int q = blockIdx.x * 128 + threadIdx.x;
    float4 qp = pc[q];
    float qx = qp.x, qy = qp.y, qz = qp.z;

    float vals[KNN]; int idxs[KNN];
    #pragma unroll
    for (int s = 0; s < KNN; s++) { vals[s] = neg_inf(); idxs[s] = 0; }

    #pragma unroll 2
    for (int j = 0; j < NPTS; j += 4) {
        float4 c0 = pc[j+0], c1 = pc[j+1], c2 = pc[j+2], c3 = pc[j+3];
        float r0 = fmaf(qx, c0.x, fmaf(qy, c0.y, fmaf(qz, c0.z, c0.w)));
        float r1 = fmaf(qx, c1.x, fmaf(qy, c1.y, fmaf(qz, c1.z, c1.w)));
        float r2 = fmaf(qx, c2.x, fmaf(qy, c2.y, fmaf(qz, c2.z, c2.w)));
        float r3 = fmaf(qx, c3.x, fmaf(qy, c3.y, fmaf(qz, c3.z, c3.w)));
        float m = fmaxf(fmaxf(r0, r1), fmaxf(r2, r3));
        if (m > vals[KNN-1]) {
            float dd[4] = {r0, r1, r2, r3};
            #pragma unroll
            for (int u = 0; u < 4; u++) {
                float d = dd[u];
                if (d > vals[KNN-1]) {
                    vals[KNN-1] = d; idxs[KNN-1] = j + u;
                    #pragma unroll
                    for (int s = KNN-1; s > 0; s--) {
                        if (vals[s] > vals[s-1]) {
                            float tv = vals[s]; vals[s] = vals[s-1]; vals[s-1] = tv;
                            int   ti = idxs[s]; idxs[s] = idxs[s-1]; idxs[s-1] = ti;
                        } else break;
                    }
                }
            }
        }
    }
    int* o = g_idx + ((size_t)b * NPTS + q) * KNN;
    #pragma unroll
    for (int s = 0; s < KNN; s++) o[s] = idxs[s];
}

// --------------- K: local_cov + mlp1 layer a (12->64 relu) -----------------
__global__ __launch_bounds__(256) void cov_l1_kernel(
    const float* __restrict__ pts,
    const float* __restrict__ W1, const float* __restrict__ b1) {
    __shared__ float sW[12*64];   // [c][o]
    __shared__ float sb[64];
    int tid = threadIdx.x;
    for (int i = tid; i < 64*12; i += 256) { int o = i / 12, c = i % 12; sW[c*64 + o] = W1[i]; }
    if (tid < 64) sb[tid] = b1[tid];
    __syncthreads();
    int w = tid >> 5, lane = tid & 31;
    int gid = blockIdx.x * 8 + w;
    int b = gid >> 11, n = gid & 2047;
    const float* p = pts + (size_t)b * NPTS * 3;
    const int* id = g_idx + (size_t)gid * KNN;
    int i0 = id[0], i1 = id[1];
    float f[12];
    f[0] = p[n*3+0]; f[1] = p[n*3+1]; f[2] = p[n*3+2];
    float a0 = p[i0*3+0], a1 = p[i0*3+1], a2 = p[i0*3+2];
    float c0 = p[i1*3+0], c1 = p[i1*3+1], c2 = p[i1*3+2];
    f[3] = a0*c0; f[4]  = a0*c1; f[5]  = a0*c2;
    f[6] = a1*c0; f[7]  = a1*c1; f[8]  = a1*c2;
    f[9] = a2*c0; f[10] = a2*c1; f[11] = a2*c2;
    float h0 = sb[lane], h1 = sb[lane+32];
    #pragma unroll
    for (int c = 0; c < 12; c++) {
        h0 = fmaf(sW[c*64 + lane],      f[c], h0);
        h1 = fmaf(sW[c*64 + lane + 32], f[c], h1);
    }
    g_t64a[(size_t)gid*64 + lane]      = fmaxf(h0, 0.f);
    g_t64a[(size_t)gid*64 + lane + 32] = fmaxf(h1, 0.f);
}

// ----------------- K: register-tiled GEMM + bias + relu --------------------
template<int K, int TILE_O>
__global__ __launch_bounds__(256) void gemm_bias_relu_kernel(
    const float* __restrict__ A, const float* __restrict__ B,
    const float* __restrict__ bias, float* __restrict__ C, int O_total) {
    constexpr int TN = 128, KC = 16, PAD = 4;
    constexpr int TO = TILE_O / 16;
    __shared__ float sA[KC][TN + PAD];
    __shared__ float sB[KC][TILE_O + PAD];
    int tid = threadIdx.x;
    int n0 = blockIdx.x * TN;
    int o0 = blockIdx.y * TILE_O;
    int nsub = tid >> 4, osub = tid & 15;
    float acc[8][TO];
    #pragma unroll
    for (int i = 0; i < 8; i++)
        #pragma unroll
        for (int j = 0; j < TO; j++) acc[i][j] = 0.f;

    float breg[TO];
    #pragma unroll
    for (int j = 0; j < TO; j++) breg[j] = bias[o0 + osub*TO + j];

    for (int k0 = 0; k0 < K; k0 += KC) {
        __syncthreads();
        {
            int n_l = tid >> 1, k_l = (tid & 1) * 8;
            const float4* p = (const float4*)(A + (size_t)(n0 + n_l) * K + k0 + k_l);
            float4 v0 = p[0], v1 = p[1];
            sA[k_l+0][n_l] = v0.x; sA[k_l+1][n_l] = v0.y;
            sA[k_l+2][n_l] = v0.z; sA[k_l+3][n_l] = v0.w;
            sA[k_l+4][n_l] = v1.x; sA[k_l+5][n_l] = v1.y;
            sA[k_l+6][n_l] = v1.z; sA[k_l+7][n_l] = v1.w;
        }
        if constexpr (TILE_O == 128) {
            int o_l = tid >> 1, k_l = (tid & 1) * 8;
            const float4* p = (const float4*)(B + (size_t)(o0 + o_l) * K + k0 + k_l);
            float4 v0 = p[0], v1 = p[1];
            sB[k_l+0][o_l] = v0.x; sB[k_l+1][o_l] = v0.y;
            sB[k_l+2][o_l] = v0.z; sB[k_l+3][o_l] = v0.w;
            sB[k_l+4][o_l] = v1.x; sB[k_l+5][o_l] = v1.y;
            sB[k_l+6][o_l] = v1.z; sB[k_l+7][o_l] = v1.w;
        } else {
            int o_l = tid >> 2, k_l = (tid & 3) * 4;
            float4 v = *(const float4*)(B + (size_t)(o0 + o_l) * K + k0 + k_l);
            sB[k_l+0][o_l] = v.x; sB[k_l+1][o_l] = v.y;
            sB[k_l+2][o_l] = v.z; sB[k_l+3][o_l] = v.w;
        }
        __syncthreads();
        #pragma unroll
        for (int kk = 0; kk < KC; kk++) {
            float4 a0 = *(const float4*)&sA[kk][nsub*8];
            float4 a1 = *(const float4*)&sA[kk][nsub*8+4];
            float af[8] = {a0.x,a0.y,a0.z,a0.w,a1.x,a1.y,a1.z,a1.w};
            float bf[TO];
            if constexpr (TO == 8) {
                float4 b0 = *(const float4*)&sB[kk][osub*8];
                float4 b1 = *(const float4*)&sB[kk][osub*8+4];
                bf[0]=b0.x; bf[1]=b0.y; bf[2]=b0.z; bf[3]=b0.w;
                bf[4]=b1.x; bf[5]=b1.y; bf[6]=b1.z; bf[7]=b1.w;
            } else {
                float4 b0 = *(const float4*)&sB[kk][osub*4];
                bf[0]=b0.x; bf[1]=b0.y; bf[2]=b0.z; bf[3]=b0.w;
            }
            #pragma unroll
            for (int i = 0; i < 8; i++)
                #pragma unroll
                for (int j = 0; j < TO; j++)
                    acc[i][j] = fmaf(af[i], bf[j], acc[i][j]);
        }
    }
    #pragma unroll
    for (int i = 0; i < 8; i++) {
        size_t base = (size_t)(n0 + nsub*8 + i) * O_total + o0 + osub*TO;
        #pragma unroll
        for (int j = 0; j < TO; j += 4) {
            float4 v;
            v.x = fmaxf(acc[i][j+0] + breg[j+0], 0.f);
            v.y = fmaxf(acc[i][j+1] + breg[j+1], 0.f);
            v.z = fmaxf(acc[i][j+2] + breg[j+2], 0.f);
            v.w = fmaxf(acc[i][j+3] + breg[j+3], 0.f);
            *(float4*)(C + base + j) = v;
        }
    }
}

// --------- K: big GEMM (pool128 x W''^T), fused per-batch max --------------
__global__ __launch_bounds__(256) void gemm_max_kernel(
    const float* __restrict__ A, const float* __restrict__ B) {
    constexpr int TN = 128, KC = 16, PAD = 4, K = 128, TILE_O = 128;
    __shared__ float sA[KC][TN + PAD];
    __shared__ float sB[KC][TILE_O + PAD];
    int tid = threadIdx.x;
    int n0 = blockIdx.x * TN;
    int o0 = blockIdx.y * TILE_O;
    int nsub = tid >> 4, osub = tid & 15;
    float acc[8][8];
    #pragma unroll
    for (int i = 0; i < 8; i++)
        #pragma unroll
        for (int j = 0; j < 8; j++) acc[i][j] = 0.f;

    for (int k0 = 0; k0 < K; k0 += KC) {
        __syncthreads();
        {
            int n_l = tid >> 1, k_l = (tid & 1) * 8;
            const float4* p = (const float4*)(A + (size_t)(n0 + n_l) * K + k0 + k_l);
            float4 v0 = p[0], v1 = p[1];
            sA[k_l+0][n_l] = v0.x; sA[k_l+1][n_l] = v0.y;
            sA[k_l+2][n_l] = v0.z; sA[k_l+3][n_l] = v0.w;
            sA[k_l+4][n_l] = v1.x; sA[k_l+5][n_l] = v1.y;
            sA[k_l+6][n_l] = v1.z; sA[k_l+7][n_l] = v1.w;
        }
        {
            int o_l = tid >> 1, k_l = (tid & 1) * 8;
            const float4* p = (const float4*)(B + (size_t)(o0 + o_l) * K + k0 + k_l);
            float4 v0 = p[0], v1 = p[1];
            sB[k_l+0][o_l] = v0.x; sB[k_l+1][o_l] = v0.y;
            sB[k_l+2][o_l] = v0.z; sB[k_l+3][o_l] = v0.w;
            sB[k_l+4][o_l] = v1.x; sB[k_l+5][o_l] = v1.y;
            sB[k_l+6][o_l] = v1.z; sB[k_l+7][o_l] = v1.w;
        }
        __syncthreads();
        #pragma unroll
        for (int kk = 0; kk < KC; kk++) {
            float4 a0 = *(const float4*)&sA[kk][nsub*8];
            float4 a1 = *(const float4*)&sA[kk][nsub*8+4];
            float4 b0 = *(const float4*)&sB[kk][osub*8];
            float4 b1 = *(const float4*)&sB[kk][osub*8+4];
            float af[8] = {a0.x,a0.y,a0.z,a0.w,a1.x,a1.y,a1.z,a1.w};
            float bf[8] = {b0.x,b0.y,b0.z,b0.w,b1.x,b1.y,b1.z,b1.w};
            #pragma unroll
            for (int i = 0; i < 8; i++)
                #pragma unroll
                for (int j = 0; j < 8; j++)
                    acc[i][j] = fmaf(af[i], bf[j], acc[i][j]);
        }
    }
    float m[8];
    #pragma unroll
    for (int j = 0; j < 8; j++) {
        float mm = acc[0][j];
        #pragma unroll
        for (int i = 1; i < 8; i++) mm = fmaxf(mm, acc[i][j]);
        m[j] = mm;
    }
    __syncthreads();
    #pragma unroll
    for (int j = 0; j < 8; j++) sA[nsub][osub*8 + j] = m[j];
    __syncthreads();
    if (tid < 128) {
        float mm = neg_inf();
        #pragma unroll
        for (int r = 0; r < 16; r++) mm = fmaxf(mm, sA[r][tid]);
        int b = blockIdx.x >> 4;
        atomicMax(&g_gmax[b*1024 + o0 + tid], fenc(mm));
    }
}

// ----------------------------- K: pool 64 ----------------------------------
__global__ __launch_bounds__(256) void pool64_kernel() {
    int tid = threadIdx.x, w = tid >> 5, lane = tid & 31;
    int gid = blockIdx.x * 8 + w;
    int boff = (gid >> 11) << 11;
    const int* id = g_idx + (size_t)gid * KNN;
    int myid = (lane < KNN) ? id[lane] : 0;
    float m0 = neg_inf(), m1 = neg_inf();
    #pragma unroll
    for (int j = 0; j < KNN; j++) {
        int nb = __shfl_sync(0xffffffffu, myid, j);
        const float* f = g_h64a + (size_t)(boff + nb) * 64;
        m0 = fmaxf(m0, f[lane]);
        m1 = fmaxf(m1, f[lane + 32]);
    }
    g_pool64[(size_t)gid*64 + lane]      = m0;
    g_pool64[(size_t)gid*64 + lane + 32] = m1;
}

// ----------------------------- K: pool 128 ---------------------------------
__global__ __launch_bounds__(256) void pool128_kernel() {
    int tid = threadIdx.x, w = tid >> 5, lane = tid & 31;
    int gid = blockIdx.x * 8 + w;
    int boff = (gid >> 11) << 11;
    const int* id = g_idx + (size_t)gid * KNN;
    int myid = (lane < KNN) ? id[lane] : 0;
    float m0 = neg_inf(), m1 = neg_inf(), m2 = neg_inf(), m3 = neg_inf();
    #pragma unroll
    for (int j = 0; j < KNN; j++) {
        int nb = __shfl_sync(0xffffffffu, myid, j);
        const float* f = g_h128a + (size_t)(boff + nb) * 128;
        m0 = fmaxf(m0, f[lane]);
        m1 = fmaxf(m1, f[lane + 32]);
        m2 = fmaxf(m2, f[lane + 64]);
        m3 = fmaxf(m3, f[lane + 96]);
    }
    float* o = g_pool128 + (size_t)gid*128;
    o[lane] = m0; o[lane+32] = m1; o[lane+64] = m2; o[lane+96] = m3;
}

// ----------------------------- K: head MLP ---------------------------------
__global__ __launch_bounds__(512) void head_kernel(
    const float* __restrict__ W_m2a, const float* __restrict__ b_m2a,
    const float* __restrict__ W_m2b, const float* __restrict__ b_m2b,
    const float* __restrict__ W_emb, float* __restrict__ out) {
    __shared__ float sv[1024], sh1[512], sh2[512];
    int b = blockIdx.x, tid = threadIdx.x, w = tid >> 5, lane = tid & 31;
    sv[tid]       = fdec(g_gmax[b*1024 + tid])       + g_bp2[tid];
    sv[tid + 512] = fdec(g_gmax[b*1024 + tid + 512]) + g_bp2[tid + 512];
    __syncthreads();
    for (int r = 0; r < 32; r++) {
        int o = w * 32 + r;
        const float* Wr = W_m2a + (size_t)o * 1024;
        float acc = 0.f;
        #pragma unroll 8
        for (int i = 0; i < 32; i++) acc = fmaf(Wr[lane + 32*i], sv[lane + 32*i], acc);
        #pragma unroll
        for (int s = 16; s > 0; s >>= 1) acc += __shfl_xor_sync(0xffffffffu, acc, s);
        if (lane == 0) sh1[o] = fmaxf(acc + b_m2a[o], 0.f);
    }
    __syncthreads();
    for (int r = 0; r < 32; r++) {
        int o = w * 32 + r;
        const float* Wr = W_m2b + (size_t)o * 512;
        float acc = 0.f;
        #pragma unroll 8
        for (int i = 0; i < 16; i++) acc = fmaf(Wr[lane + 32*i], sh1[lane + 32*i], acc);
        #pragma unroll
        for (int s = 16; s > 0; s >>= 1) acc += __shfl_xor_sync(0xffffffffu, acc, s);
        if (lane == 0) sh2[o] = acc + b_m2b[o];
    }
    __syncthreads();
    for (int r = 0; r < 8; r++) {
        int j = w * 8 + r;
        const float* Wr = W_emb + (size_t)j * 512;
        float acc = 0.f;
        #pragma unroll 8
        for (int i = 0; i < 16; i++) acc = fmaf(Wr[lane + 32*i], sh2[lane + 32*i], acc);
        #pragma unroll
        for (int s = 16; s > 0; s >>= 1) acc += __shfl_xor_sync(0xffffffffu, acc, s);
        if (lane == 0) out[b*128 + j] = acc;
    }
}

// ----------------------------- launch --------------------------------------
extern "C" void kernel_launch(void* const* d_in, const int* in_sizes, int n_in,
                              void* d_out, int out_size) {
    const float* pts    = (const float*)d_in[0];
    const float* W_m1a  = (const float*)d_in[1];
    const float* b_m1a  = (const float*)d_in[2];
    const float* W_m1b  = (const float*)d_in[3];
    const float* b_m1b  = (const float*)d_in[4];
    const float* W_m1c  = (const float*)d_in[5];
    const float* b_m1c  = (const float*)d_in[6];
    const float* W_lin1 = (const float*)d_in[7];
    const float* b_lin1 = (const float*)d_in[8];
    const float* W_c1   = (const float*)d_in[9];
    const float* b_c1   = (const float*)d_in[10];
    const float* W_lin2 = (const float*)d_in[11];
    const float* b_lin2 = (const float*)d_in[12];
    const float* W_c2   = (const float*)d_in[13];
    const float* b_c2   = (const float*)d_in[14];
    const float* W_m2a  = (const float*)d_in[15];
    const float* b_m2a  = (const float*)d_in[16];
    const float* W_m2b  = (const float*)d_in[17];
    const float* b_m2b  = (const float*)d_in[18];
    const float* W_emb  = (const float*)d_in[19];
    float* out = (float*)d_out;

    float* t64a; cudaGetSymbolAddress((void**)&t64a, g_t64a);
    float* t64b; cudaGetSymbolAddress((void**)&t64b, g_t64b);
    float* h64a; cudaGetSymbolAddress((void**)&h64a, g_h64a);
    float* p64;  cudaGetSymbolAddress((void**)&p64,  g_pool64);
    float* h128; cudaGetSymbolAddress((void**)&h128, g_h128a);
    float* p128; cudaGetSymbolAddress((void**)&p128, g_pool128);
    float* wp1;  cudaGetSymbolAddress((void**)&wp1,  g_Wp1);
    float* bp1;  cudaGetSymbolAddress((void**)&bp1,  g_bp1);
    float* wp2;  cudaGetSymbolAddress((void**)&wp2,  g_Wp2);

    zero_gmax_kernel<<<BATCH, 1024>>>();
    prep_wp1_kernel<<<32, 256>>>(W_c1, W_lin1, b_lin1, b_c1);
    prep_wp2_kernel<<<1024, 128>>>(W_c2, W_lin2, b_lin2, b_c2);

    knn_kernel<<<dim3(NPTS/128, BATCH), 128>>>(pts);
    cov_l1_kernel<<<NPT/8, 256>>>(pts, W_m1a, b_m1a);

    gemm_bias_relu_kernel<64, 64><<<dim3(NPT/128, 1), 256>>>(t64a, W_m1b, b_m1b, t64b, 64);
    gemm_bias_relu_kernel<64, 64><<<dim3(NPT/128, 1), 256>>>(t64b, W_m1c, b_m1c, h64a, 64);

    pool64_kernel<<<NPT/8, 256>>>();
    gemm_bias_relu_kernel<64, 128><<<dim3(NPT/128, 1), 256>>>(p64, wp1, bp1, h128, 128);

    pool128_kernel<<<NPT/8, 256>>>();
    gemm_max_kernel<<<dim3(NPT/128, 8), 256>>>(p128, wp2);

    head_kernel<<<BATCH, 512>>>(W_m2a, b_m2a, W_m2b, b_m2b, W_emb, out);
}

// round 10
// speedup vs baseline: 5.8931x; 3.5957x over previous
#include <cuda_runtime.h>
#include <cuda_bf16.h>
#include <cstdint>

#define BATCH 16
#define NPTS  2048
#define KNN   16
#define NPT   (BATCH*NPTS)

// ----------------------------- scratch ------------------------------------
__device__ __align__(16) int      g_idx[NPT*KNN];
__device__ __align__(16) float    g_t64a[NPT*64];
__device__ __align__(16) float    g_t64b[NPT*64];
__device__ __align__(16) float    g_h64a[NPT*64];
__device__ __align__(16) float    g_pool64[NPT*64];
__device__ __align__(16) float    g_h128a[NPT*128];
__device__ __align__(16) float    g_pool128[NPT*128];
__device__ __align__(16) float    g_Wp1[128*64];   // (Wc1@Wlin1)[o][c]
__device__ __align__(16) float    g_bp1[128];
__device__ __align__(16) float    g_Wp2[1024*128]; // (Wc2@Wlin2)[o][c]
__device__ __align__(16) float    g_bp2[1024];
__device__ __align__(16) unsigned g_gmax[BATCH*1024];

__device__ __forceinline__ unsigned fenc(float f) {
    unsigned b = __float_as_uint(f);
    return (b & 0x80000000u) ? ~b : (b | 0x80000000u);
}
__device__ __forceinline__ float fdec(unsigned u) {
    return __uint_as_float((u & 0x80000000u) ? (u ^ 0x80000000u) : ~u);
}
__device__ __forceinline__ float neg_inf() { return __uint_as_float(0xff800000u); }

// ----------------------------- K: zero gmax --------------------------------
__global__ void zero_gmax_kernel() {
    g_gmax[blockIdx.x * 1024 + threadIdx.x] = 0u;
}

// ------------------- K: precompute W' = Wc1 @ Wlin1 ------------------------
__global__ __launch_bounds__(256) void prep_wp1_kernel(
    const float* __restrict__ Wc1, const float* __restrict__ Wlin1,
    const float* __restrict__ b_lin1, const float* __restrict__ b_c1) {
    int g = blockIdx.x * 256 + threadIdx.x;          // 8192
    int o = g >> 6, c = g & 63;
    float acc = 0.f;
    for (int m = 0; m < 64; m++) acc = fmaf(Wc1[o*64+m], Wlin1[m*64+c], acc);
    g_Wp1[o*64 + c] = acc;
    if (c == 0) {
        float bb = b_c1[o];
        for (int m = 0; m < 64; m++) bb = fmaf(Wc1[o*64+m], b_lin1[m], bb);
        g_bp1[o] = bb;
    }
}

// ------------------- K: precompute W'' = Wc2 @ Wlin2 -----------------------
__global__ __launch_bounds__(128) void prep_wp2_kernel(
    const float* __restrict__ Wc2, const float* __restrict__ Wlin2,
    const float* __restrict__ b_lin2, const float* __restrict__ b_c2) {
    int o = blockIdx.x, c = threadIdx.x;
    float acc = 0.f;
    for (int m = 0; m < 128; m++) acc = fmaf(Wc2[o*128+m], Wlin2[m*128+c], acc);
    g_Wp2[o*128 + c] = acc;
    if (c == 0) {
        float bb = b_c2[o];
        for (int m = 0; m < 128; m++) bb = fmaf(Wc2[o*128+m], b_lin2[m], bb);
        g_bp2[o] = bb;
    }
}

// ----------------------------- K: kNN ---------------------------------------
// One thread per query, 256-thread blocks (R2-proven geometry).
// Rank by r = qx*x + qy*y + qz*z - 0.5*|p|^2  (d = 2r - qxx monotone in r per
// query => same top-k set/order as neg squared distance; verified bit-identical
// outputs in R7/R9 benches).
// Top-16 kept UNSORTED with a register threshold; insertion is a branchless
// min-slot replace (SEL/FMNMX only, compile-time register indices) so the
// divergence-serialized taken path is ~110 instr with no nested BSSY regions.
// Final order (value desc, tie -> smaller idx) emitted by repeated extraction.
__global__ __launch_bounds__(256) void knn_kernel(const float* __restrict__ pts) {
    __shared__ __align__(16) float2 sxy[NPTS];   // (x, y)
    __shared__ __align__(16) float2 szh[NPTS];   // (z, -0.5*|p|^2)
    int b = blockIdx.y;
    const float* p = pts + (size_t)b * NPTS * 3;
    for (int i = threadIdx.x; i < NPTS; i += 256) {
        float x = p[i*3+0], y = p[i*3+1], z = p[i*3+2];
        float h = -0.5f * fmaf(z, z, fmaf(y, y, x * x));
        sxy[i] = make_float2(x, y);
        szh[i] = make_float2(z, h);
    }
    __syncthreads();
    int q = blockIdx.x * 256 + threadIdx.x;
    float2 qxy = sxy[q];
    float qx = qxy.x, qy = qxy.y, qz = szh[q].x;

    float vals[KNN]; int idxs[KNN];
    #pragma unroll
    for (int s = 0; s < KNN; s++) { vals[s] = neg_inf(); idxs[s] = 0; }
    float curmin = neg_inf();

    for (int j = 0; j < NPTS; j++) {
        float2 cxy = sxy[j], czh = szh[j];
        float r = fmaf(qx, cxy.x, fmaf(qy, cxy.y, fmaf(qz, czh.x, czh.y)));
        if (r > curmin) {
            // locate current min slot (branchless; first-min on ties)
            int pos = 0; float mv = vals[0];
            #pragma unroll
            for (int s = 1; s < KNN; s++) {
                bool lt = vals[s] < mv;
                mv  = lt ? vals[s] : mv;
                pos = lt ? s : pos;
            }
            // replace it (compile-time indices -> stays in registers)
            #pragma unroll
            for (int s = 0; s < KNN; s++) {
                bool sel = (s == pos);
                vals[s] = sel ? r : vals[s];
                idxs[s] = sel ? j : idxs[s];
            }
            // refresh threshold
            float nm = vals[0];
            #pragma unroll
            for (int s = 1; s < KNN; s++) nm = fminf(nm, vals[s]);
            curmin = nm;
        }
    }

    // emit sorted: value desc, tie -> smaller index (jax.lax.top_k order)
    int* o = g_idx + ((size_t)b * NPTS + q) * KNN;
    #pragma unroll
    for (int s = 0; s < KNN; s++) {
        float bv = vals[0]; int bi = idxs[0]; int bp = 0;
        #pragma unroll
        for (int t = 1; t < KNN; t++) {
            bool better = (vals[t] > bv) || (vals[t] == bv && idxs[t] < bi);
            bv = better ? vals[t] : bv;
            bi = better ? idxs[t] : bi;
            bp = better ? t : bp;
        }
        o[s] = bi;
        #pragma unroll
        for (int t = 0; t < KNN; t++) {
            bool kill = (t == bp);
            vals[t] = kill ? neg_inf() : vals[t];
        }
    }
}

// --------------- K: local_cov + mlp1 layer a (12->64 relu) -----------------
__global__ __launch_bounds__(256) void cov_l1_kernel(
    const float* __restrict__ pts,
    const float* __restrict__ W1, const float* __restrict__ b1) {
    __shared__ float sW[12*64];   // [c][o]
    __shared__ float sb[64];
    int tid = threadIdx.x;
    for (int i = tid; i < 64*12; i += 256) { int o = i / 12, c = i % 12; sW[c*64 + o] = W1[i]; }
    if (tid < 64) sb[tid] = b1[tid];
    __syncthreads();
    int w = tid >> 5, lane = tid & 31;
    int gid = blockIdx.x * 8 + w;
    int b = gid >> 11, n = gid & 2047;
    const float* p = pts + (size_t)b * NPTS * 3;
    const int* id = g_idx + (size_t)gid * KNN;
    int i0 = id[0], i1 = id[1];
    float f[12];
    f[0] = p[n*3+0]; f[1] = p[n*3+1]; f[2] = p[n*3+2];
    float a0 = p[i0*3+0], a1 = p[i0*3+1], a2 = p[i0*3+2];
    float c0 = p[i1*3+0], c1 = p[i1*3+1], c2 = p[i1*3+2];
    f[3] = a0*c0; f[4]  = a0*c1; f[5]  = a0*c2;
    f[6] = a1*c0; f[7]  = a1*c1; f[8]  = a1*c2;
    f[9] = a2*c0; f[10] = a2*c1; f[11] = a2*c2;
    float h0 = sb[lane], h1 = sb[lane+32];
    #pragma unroll
    for (int c = 0; c < 12; c++) {
        h0 = fmaf(sW[c*64 + lane],      f[c], h0);
        h1 = fmaf(sW[c*64 + lane + 32], f[c], h1);
    }
    g_t64a[(size_t)gid*64 + lane]      = fmaxf(h0, 0.f);
    g_t64a[(size_t)gid*64 + lane + 32] = fmaxf(h1, 0.f);
}

// ----------------- K: register-tiled GEMM + bias + relu --------------------
template<int K, int TILE_O>
__global__ __launch_bounds__(256) void gemm_bias_relu_kernel(
    const float* __restrict__ A, const float* __restrict__ B,
    const float* __restrict__ bias, float* __restrict__ C, int O_total) {
    constexpr int TN = 128, KC = 16, PAD = 4;
    constexpr int TO = TILE_O / 16;
    __shared__ float sA[KC][TN + PAD];
    __shared__ float sB[KC][TILE_O + PAD];
    int tid = threadIdx.x;
    int n0 = blockIdx.x * TN;
    int o0 = blockIdx.y * TILE_O;
    int nsub = tid >> 4, osub = tid & 15;
    float acc[8][TO];
    #pragma unroll
    for (int i = 0; i < 8; i++)
        #pragma unroll
        for (int j = 0; j < TO; j++) acc[i][j] = 0.f;

    float breg[TO];
    #pragma unroll
    for (int j = 0; j < TO; j++) breg[j] = bias[o0 + osub*TO + j];

    for (int k0 = 0; k0 < K; k0 += KC) {
        __syncthreads();
        {
            int n_l = tid >> 1, k_l = (tid & 1) * 8;
            const float4* p = (const float4*)(A + (size_t)(n0 + n_l) * K + k0 + k_l);
            float4 v0 = p[0], v1 = p[1];
            sA[k_l+0][n_l] = v0.x; sA[k_l+1][n_l] = v0.y;
            sA[k_l+2][n_l] = v0.z; sA[k_l+3][n_l] = v0.w;
            sA[k_l+4][n_l] = v1.x; sA[k_l+5][n_l] = v1.y;
            sA[k_l+6][n_l] = v1.z; sA[k_l+7][n_l] = v1.w;
        }
        if constexpr (TILE_O == 128) {
            int o_l = tid >> 1, k_l = (tid & 1) * 8;
            const float4* p = (const float4*)(B + (size_t)(o0 + o_l) * K + k0 + k_l);
            float4 v0 = p[0], v1 = p[1];
            sB[k_l+0][o_l] = v0.x; sB[k_l+1][o_l] = v0.y;
            sB[k_l+2][o_l] = v0.z; sB[k_l+3][o_l] = v0.w;
            sB[k_l+4][o_l] = v1.x; sB[k_l+5][o_l] = v1.y;
            sB[k_l+6][o_l] = v1.z; sB[k_l+7][o_l] = v1.w;
        } else {
            int o_l = tid >> 2, k_l = (tid & 3) * 4;
            float4 v = *(const float4*)(B + (size_t)(o0 + o_l) * K + k0 + k_l);
            sB[k_l+0][o_l] = v.x; sB[k_l+1][o_l] = v.y;
            sB[k_l+2][o_l] = v.z; sB[k_l+3][o_l] = v.w;
        }
        __syncthreads();
        #pragma unroll
        for (int kk = 0; kk < KC; kk++) {
            float4 a0 = *(const float4*)&sA[kk][nsub*8];
            float4 a1 = *(const float4*)&sA[kk][nsub*8+4];
            float af[8] = {a0.x,a0.y,a0.z,a0.w,a1.x,a1.y,a1.z,a1.w};
            float bf[TO];
            if constexpr (TO == 8) {
                float4 b0 = *(const float4*)&sB[kk][osub*8];
                float4 b1 = *(const float4*)&sB[kk][osub*8+4];
                bf[0]=b0.x; bf[1]=b0.y; bf[2]=b0.z; bf[3]=b0.w;
                bf[4]=b1.x; bf[5]=b1.y; bf[6]=b1.z; bf[7]=b1.w;
            } else {
                float4 b0 = *(const float4*)&sB[kk][osub*4];
                bf[0]=b0.x; bf[1]=b0.y; bf[2]=b0.z; bf[3]=b0.w;
            }
            #pragma unroll
            for (int i = 0; i < 8; i++)
                #pragma unroll
                for (int j = 0; j < TO; j++)
                    acc[i][j] = fmaf(af[i], bf[j], acc[i][j]);
        }
    }
    #pragma unroll
    for (int i = 0; i < 8; i++) {
        size_t base = (size_t)(n0 + nsub*8 + i) * O_total + o0 + osub*TO;
        #pragma unroll
        for (int j = 0; j < TO; j += 4) {
            float4 v;
            v.x = fmaxf(acc[i][j+0] + breg[j+0], 0.f);
            v.y = fmaxf(acc[i][j+1] + breg[j+1], 0.f);
            v.z = fmaxf(acc[i][j+2] + breg[j+2], 0.f);
            v.w = fmaxf(acc[i][j+3] + breg[j+3], 0.f);
            *(float4*)(C + base + j) = v;
        }
    }
}

// --------- K: big GEMM (pool128 x W''^T), fused per-batch max --------------
__global__ __launch_bounds__(256) void gemm_max_kernel(
    const float* __restrict__ A, const float* __restrict__ B) {
    constexpr int TN = 128, KC = 16, PAD = 4, K = 128, TILE_O = 128;
    __shared__ float sA[KC][TN + PAD];
    __shared__ float sB[KC][TILE_O + PAD];
    int tid = threadIdx.x;
    int n0 = blockIdx.x * TN;
    int o0 = blockIdx.y * TILE_O;
    int nsub = tid >> 4, osub = tid & 15;
    float acc[8][8];
    #pragma unroll
    for (int i = 0; i < 8; i++)
        #pragma unroll
        for (int j = 0; j < 8; j++) acc[i][j] = 0.f;

    for (int k0 = 0; k0 < K; k0 += KC) {
        __syncthreads();
        {
            int n_l = tid >> 1, k_l = (tid & 1) * 8;
            const float4* p = (const float4*)(A + (size_t)(n0 + n_l) * K + k0 + k_l);
            float4 v0 = p[0], v1 = p[1];
            sA[k_l+0][n_l] = v0.x; sA[k_l+1][n_l] = v0.y;
            sA[k_l+2][n_l] = v0.z; sA[k_l+3][n_l] = v0.w;
            sA[k_l+4][n_l] = v1.x; sA[k_l+5][n_l] = v1.y;
            sA[k_l+6][n_l] = v1.z; sA[k_l+7][n_l] = v1.w;
        }
        {
            int o_l = tid >> 1, k_l = (tid & 1) * 8;
            const float4* p = (const float4*)(B + (size_t)(o0 + o_l) * K + k0 + k_l);
            float4 v0 = p[0], v1 = p[1];
            sB[k_l+0][o_l] = v0.x; sB[k_l+1][o_l] = v0.y;
            sB[k_l+2][o_l] = v0.z; sB[k_l+3][o_l] = v0.w;
            sB[k_l+4][o_l] = v1.x; sB[k_l+5][o_l] = v1.y;
            sB[k_l+6][o_l] = v1.z; sB[k_l+7][o_l] = v1.w;
        }
        __syncthreads();
        #pragma unroll
        for (int kk = 0; kk < KC; kk++) {
            float4 a0 = *(const float4*)&sA[kk][nsub*8];
            float4 a1 = *(const float4*)&sA[kk][nsub*8+4];
            float4 b0 = *(const float4*)&sB[kk][osub*8];
            float4 b1 = *(const float4*)&sB[kk][osub*8+4];
            float af[8] = {a0.x,a0.y,a0.z,a0.w,a1.x,a1.y,a1.z,a1.w};
            float bf[8] = {b0.x,b0.y,b0.z,b0.w,b1.x,b1.y,b1.z,b1.w};
            #pragma unroll
            for (int i = 0; i < 8; i++)
                #pragma unroll
                for (int j = 0; j < 8; j++)
                    acc[i][j] = fmaf(af[i], bf[j], acc[i][j]);
        }
    }
    float m[8];
    #pragma unroll
    for (int j = 0; j < 8; j++) {
        float mm = acc[0][j];
        #pragma unroll
        for (int i = 1; i < 8; i++) mm = fmaxf(mm, acc[i][j]);
        m[j] = mm;
    }
    __syncthreads();
    #pragma unroll
    for (int j = 0; j < 8; j++) sA[nsub][osub*8 + j] = m[j];
    __syncthreads();
    if (tid < 128) {
        float mm = neg_inf();
        #pragma unroll
        for (int r = 0; r < 16; r++) mm = fmaxf(mm, sA[r][tid]);
        int b = blockIdx.x >> 4;
        atomicMax(&g_gmax[b*1024 + o0 + tid], fenc(mm));
    }
}

// ----------------------------- K: pool 64 ----------------------------------
__global__ __launch_bounds__(256) void pool64_kernel() {
    int tid = threadIdx.x, w = tid >> 5, lane = tid & 31;
    int gid = blockIdx.x * 8 + w;
    int boff = (gid >> 11) << 11;
    const int* id = g_idx + (size_t)gid * KNN;
    int myid = (lane < KNN) ? id[lane] : 0;
    float m0 = neg_inf(), m1 = neg_inf();
    #pragma unroll
    for (int j = 0; j < KNN; j++) {
        int nb = __shfl_sync(0xffffffffu, myid, j);
        const float* f = g_h64a + (size_t)(boff + nb) * 64;
        m0 = fmaxf(m0, f[lane]);
        m1 = fmaxf(m1, f[lane + 32]);
    }
    g_pool64[(size_t)gid*64 + lane]      = m0;
    g_pool64[(size_t)gid*64 + lane + 32] = m1;
}

// ----------------------------- K: pool 128 ---------------------------------
__global__ __launch_bounds__(256) void pool128_kernel() {
    int tid = threadIdx.x, w = tid >> 5, lane = tid & 31;
    int gid = blockIdx.x * 8 + w;
    int boff = (gid >> 11) << 11;
    const int* id = g_idx + (size_t)gid * KNN;
    int myid = (lane < KNN) ? id[lane] : 0;
    float m0 = neg_inf(), m1 = neg_inf(), m2 = neg_inf(), m3 = neg_inf();
    #pragma unroll
    for (int j = 0; j < KNN; j++) {
        int nb = __shfl_sync(0xffffffffu, myid, j);
        const float* f = g_h128a + (size_t)(boff + nb) * 128;
        m0 = fmaxf(m0, f[lane]);
        m1 = fmaxf(m1, f[lane + 32]);
        m2 = fmaxf(m2, f[lane + 64]);
        m3 = fmaxf(m3, f[lane + 96]);
    }
    float* o = g_pool128 + (size_t)gid*128;
    o[lane] = m0; o[lane+32] = m1; o[lane+64] = m2; o[lane+96] = m3;
}

// ----------------------------- K: head MLP ---------------------------------
__global__ __launch_bounds__(512) void head_kernel(
    const float* __restrict__ W_m2a, const float* __restrict__ b_m2a,
    const float* __restrict__ W_m2b, const float* __restrict__ b_m2b,
    const float* __restrict__ W_emb, float* __restrict__ out) {
    __shared__ float sv[1024], sh1[512], sh2[512];
    int b = blockIdx.x, tid = threadIdx.x, w = tid >> 5, lane = tid & 31;
    sv[tid]       = fdec(g_gmax[b*1024 + tid])       + g_bp2[tid];
    sv[tid + 512] = fdec(g_gmax[b*1024 + tid + 512]) + g_bp2[tid + 512];
    __syncthreads();
    for (int r = 0; r < 32; r++) {
        int o = w * 32 + r;
        const float* Wr = W_m2a + (size_t)o * 1024;
        float acc = 0.f;
        #pragma unroll 8
        for (int i = 0; i < 32; i++) acc = fmaf(Wr[lane + 32*i], sv[lane + 32*i], acc);
        #pragma unroll
        for (int s = 16; s > 0; s >>= 1) acc += __shfl_xor_sync(0xffffffffu, acc, s);
        if (lane == 0) sh1[o] = fmaxf(acc + b_m2a[o], 0.f);
    }
    __syncthreads();
    for (int r = 0; r < 32; r++) {
        int o = w * 32 + r;
        const float* Wr = W_m2b + (size_t)o * 512;
        float acc = 0.f;
        #pragma unroll 8
        for (int i = 0; i < 16; i++) acc = fmaf(Wr[lane + 32*i], sh1[lane + 32*i], acc);
        #pragma unroll
        for (int s = 16; s > 0; s >>= 1) acc += __shfl_xor_sync(0xffffffffu, acc, s);
        if (lane == 0) sh2[o] = acc + b_m2b[o];
    }
    __syncthreads();
    for (int r = 0; r < 8; r++) {
        int j = w * 8 + r;
        const float* Wr = W_emb + (size_t)j * 512;
        float acc = 0.f;
        #pragma unroll 8
        for (int i = 0; i < 16; i++) acc = fmaf(Wr[lane + 32*i], sh2[lane + 32*i], acc);
        #pragma unroll
        for (int s = 16; s > 0; s >>= 1) acc += __shfl_xor_sync(0xffffffffu, acc, s);
        if (lane == 0) out[b*128 + j] = acc;
    }
}

// ----------------------------- launch --------------------------------------
extern "C" void kernel_launch(void* const* d_in, const int* in_sizes, int n_in,
                              void* d_out, int out_size) {
    const float* pts    = (const float*)d_in[0];
    const float* W_m1a  = (const float*)d_in[1];
    const float* b_m1a  = (const float*)d_in[2];
    const float* W_m1b  = (const float*)d_in[3];
    const float* b_m1b  = (const float*)d_in[4];
    const float* W_m1c  = (const float*)d_in[5];
    const float* b_m1c  = (const float*)d_in[6];
    const float* W_lin1 = (const float*)d_in[7];
    const float* b_lin1 = (const float*)d_in[8];
    const float* W_c1   = (const float*)d_in[9];
    const float* b_c1   = (const float*)d_in[10];
    const float* W_lin2 = (const float*)d_in[11];
    const float* b_lin2 = (const float*)d_in[12];
    const float* W_c2   = (const float*)d_in[13];
    const float* b_c2   = (const float*)d_in[14];
    const float* W_m2a  = (const float*)d_in[15];
    const float* b_m2a  = (const float*)d_in[16];
    const float* W_m2b  = (const float*)d_in[17];
    const float* b_m2b  = (const float*)d_in[18];
    const float* W_emb  = (const float*)d_in[19];
    float* out = (float*)d_out;

    float* t64a; cudaGetSymbolAddress((void**)&t64a, g_t64a);
    float* t64b; cudaGetSymbolAddress((void**)&t64b, g_t64b);
    float* h64a; cudaGetSymbolAddress((void**)&h64a, g_h64a);
    float* p64;  cudaGetSymbolAddress((void**)&p64,  g_pool64);
    float* h128; cudaGetSymbolAddress((void**)&h128, g_h128a);
    float* p128; cudaGetSymbolAddress((void**)&p128, g_pool128);
    float* wp1;  cudaGetSymbolAddress((void**)&wp1,  g_Wp1);
    float* bp1;  cudaGetSymbolAddress((void**)&bp1,  g_bp1);
    float* wp2;  cudaGetSymbolAddress((void**)&wp2,  g_Wp2);

    zero_gmax_kernel<<<BATCH, 1024>>>();
    prep_wp1_kernel<<<32, 256>>>(W_c1, W_lin1, b_lin1, b_c1);
    prep_wp2_kernel<<<1024, 128>>>(W_c2, W_lin2, b_lin2, b_c2);

    knn_kernel<<<dim3(NPTS/256, BATCH), 256>>>(pts);
    cov_l1_kernel<<<NPT/8, 256>>>(pts, W_m1a, b_m1a);

    gemm_bias_relu_kernel<64, 64><<<dim3(NPT/128, 1), 256>>>(t64a, W_m1b, b_m1b, t64b, 64);
    gemm_bias_relu_kernel<64, 64><<<dim3(NPT/128, 1), 256>>>(t64b, W_m1c, b_m1c, h64a, 64);

    pool64_kernel<<<NPT/8, 256>>>();
    gemm_bias_relu_kernel<64, 128><<<dim3(NPT/128, 1), 256>>>(p64, wp1, bp1, h128, 128);

    pool128_kernel<<<NPT/8, 256>>>();
    gemm_max_kernel<<<dim3(NPT/128, 8), 256>>>(p128, wp2);

    head_kernel<<<BATCH, 512>>>(W_m2a, b_m2a, W_m2b, b_m2b, W_emb, out);
}

// round 11
// speedup vs baseline: 6.8390x; 1.1605x over previous
#include <cuda_runtime.h>
#include <cuda_bf16.h>
#include <cstdint>

#define BATCH 16
#define NPTS  2048
#define KNN   16
#define NPT   (BATCH*NPTS)

// ----------------------------- scratch ------------------------------------
__device__ __align__(16) int      g_idx[NPT*KNN];
__device__ __align__(16) float    g_t64a[NPT*64];
__device__ __align__(16) float    g_t64b[NPT*64];
__device__ __align__(16) float    g_h64a[NPT*64];
__device__ __align__(16) float    g_pool64[NPT*64];
__device__ __align__(16) float    g_h128a[NPT*128];
__device__ __align__(16) float    g_Wp1[128*64];   // (Wc1@Wlin1)[o][c]
__device__ __align__(16) float    g_bp1[128];
__device__ __align__(16) float    g_bp2[1024];
__device__ __align__(16) unsigned g_gmax[BATCH*1024];
// bf16 hi/lo splits feeding the tensor-core gemm_max
__device__ __align__(16) __nv_bfloat16 g_p128h[NPT*128];
__device__ __align__(16) __nv_bfloat16 g_p128l[NPT*128];
__device__ __align__(16) __nv_bfloat16 g_Wp2h[1024*128];
__device__ __align__(16) __nv_bfloat16 g_Wp2l[1024*128];

__device__ __forceinline__ unsigned fenc(float f) {
    unsigned b = __float_as_uint(f);
    return (b & 0x80000000u) ? ~b : (b | 0x80000000u);
}
__device__ __forceinline__ float fdec(unsigned u) {
    return __uint_as_float((u & 0x80000000u) ? (u ^ 0x80000000u) : ~u);
}
__device__ __forceinline__ float neg_inf() { return __uint_as_float(0xff800000u); }

// ----------------------------- K: zero gmax --------------------------------
__global__ void zero_gmax_kernel() {
    g_gmax[blockIdx.x * 1024 + threadIdx.x] = 0u;
}

// ------------------- K: precompute W' = Wc1 @ Wlin1 ------------------------
__global__ __launch_bounds__(256) void prep_wp1_kernel(
    const float* __restrict__ Wc1, const float* __restrict__ Wlin1,
    const float* __restrict__ b_lin1, const float* __restrict__ b_c1) {
    int g = blockIdx.x * 256 + threadIdx.x;          // 8192
    int o = g >> 6, c = g & 63;
    float acc = 0.f;
    for (int m = 0; m < 64; m++) acc = fmaf(Wc1[o*64+m], Wlin1[m*64+c], acc);
    g_Wp1[o*64 + c] = acc;
    if (c == 0) {
        float bb = b_c1[o];
        for (int m = 0; m < 64; m++) bb = fmaf(Wc1[o*64+m], b_lin1[m], bb);
        g_bp1[o] = bb;
    }
}

// --------- K: precompute W'' = Wc2 @ Wlin2, emit bf16 hi/lo split ----------
__global__ __launch_bounds__(128) void prep_wp2_kernel(
    const float* __restrict__ Wc2, const float* __restrict__ Wlin2,
    const float* __restrict__ b_lin2, const float* __restrict__ b_c2) {
    int o = blockIdx.x, c = threadIdx.x;
    float acc = 0.f;
    for (int m = 0; m < 128; m++) acc = fmaf(Wc2[o*128+m], Wlin2[m*128+c], acc);
    __nv_bfloat16 h = __float2bfloat16(acc);
    g_Wp2h[o*128 + c] = h;
    g_Wp2l[o*128 + c] = __float2bfloat16(acc - __bfloat162float(h));
    if (c == 0) {
        float bb = b_c2[o];
        for (int m = 0; m < 128; m++) bb = fmaf(Wc2[o*128+m], b_lin2[m], bb);
        g_bp2[o] = bb;
    }
}

// ----------------------------- K: kNN ---------------------------------------
// (unchanged from the 664us R10 kernel)
__global__ __launch_bounds__(256) void knn_kernel(const float* __restrict__ pts) {
    __shared__ __align__(16) float2 sxy[NPTS];
    __shared__ __align__(16) float2 szh[NPTS];
    int b = blockIdx.y;
    const float* p = pts + (size_t)b * NPTS * 3;
    for (int i = threadIdx.x; i < NPTS; i += 256) {
        float x = p[i*3+0], y = p[i*3+1], z = p[i*3+2];
        float h = -0.5f * fmaf(z, z, fmaf(y, y, x * x));
        sxy[i] = make_float2(x, y);
        szh[i] = make_float2(z, h);
    }
    __syncthreads();
    int q = blockIdx.x * 256 + threadIdx.x;
    float2 qxy = sxy[q];
    float qx = qxy.x, qy = qxy.y, qz = szh[q].x;

    float vals[KNN]; int idxs[KNN];
    #pragma unroll
    for (int s = 0; s < KNN; s++) { vals[s] = neg_inf(); idxs[s] = 0; }
    float curmin = neg_inf();

    for (int j = 0; j < NPTS; j++) {
        float2 cxy = sxy[j], czh = szh[j];
        float r = fmaf(qx, cxy.x, fmaf(qy, cxy.y, fmaf(qz, czh.x, czh.y)));
        if (r > curmin) {
            int pos = 0; float mv = vals[0];
            #pragma unroll
            for (int s = 1; s < KNN; s++) {
                bool lt = vals[s] < mv;
                mv  = lt ? vals[s] : mv;
                pos = lt ? s : pos;
            }
            #pragma unroll
            for (int s = 0; s < KNN; s++) {
                bool sel = (s == pos);
                vals[s] = sel ? r : vals[s];
                idxs[s] = sel ? j : idxs[s];
            }
            float nm = vals[0];
            #pragma unroll
            for (int s = 1; s < KNN; s++) nm = fminf(nm, vals[s]);
            curmin = nm;
        }
    }

    int* o = g_idx + ((size_t)b * NPTS + q) * KNN;
    #pragma unroll
    for (int s = 0; s < KNN; s++) {
        float bv = vals[0]; int bi = idxs[0]; int bp = 0;
        #pragma unroll
        for (int t = 1; t < KNN; t++) {
            bool better = (vals[t] > bv) || (vals[t] == bv && idxs[t] < bi);
            bv = better ? vals[t] : bv;
            bi = better ? idxs[t] : bi;
            bp = better ? t : bp;
        }
        o[s] = bi;
        #pragma unroll
        for (int t = 0; t < KNN; t++) {
            bool kill = (t == bp);
            vals[t] = kill ? neg_inf() : vals[t];
        }
    }
}

// --------------- K: local_cov + mlp1 layer a (12->64 relu) -----------------
__global__ __launch_bounds__(256) void cov_l1_kernel(
    const float* __restrict__ pts,
    const float* __restrict__ W1, const float* __restrict__ b1) {
    __shared__ float sW[12*64];
    __shared__ float sb[64];
    int tid = threadIdx.x;
    for (int i = tid; i < 64*12; i += 256) { int o = i / 12, c = i % 12; sW[c*64 + o] = W1[i]; }
    if (tid < 64) sb[tid] = b1[tid];
    __syncthreads();
    int w = tid >> 5, lane = tid & 31;
    int gid = blockIdx.x * 8 + w;
    int b = gid >> 11, n = gid & 2047;
    const float* p = pts + (size_t)b * NPTS * 3;
    const int* id = g_idx + (size_t)gid * KNN;
    int i0 = id[0], i1 = id[1];
    float f[12];
    f[0] = p[n*3+0]; f[1] = p[n*3+1]; f[2] = p[n*3+2];
    float a0 = p[i0*3+0], a1 = p[i0*3+1], a2 = p[i0*3+2];
    float c0 = p[i1*3+0], c1 = p[i1*3+1], c2 = p[i1*3+2];
    f[3] = a0*c0; f[4]  = a0*c1; f[5]  = a0*c2;
    f[6] = a1*c0; f[7]  = a1*c1; f[8]  = a1*c2;
    f[9] = a2*c0; f[10] = a2*c1; f[11] = a2*c2;
    float h0 = sb[lane], h1 = sb[lane+32];
    #pragma unroll
    for (int c = 0; c < 12; c++) {
        h0 = fmaf(sW[c*64 + lane],      f[c], h0);
        h1 = fmaf(sW[c*64 + lane + 32], f[c], h1);
    }
    g_t64a[(size_t)gid*64 + lane]      = fmaxf(h0, 0.f);
    g_t64a[(size_t)gid*64 + lane + 32] = fmaxf(h1, 0.f);
}

// ----------------- K: register-tiled GEMM + bias + relu --------------------
template<int K, int TILE_O>
__global__ __launch_bounds__(256) void gemm_bias_relu_kernel(
    const float* __restrict__ A, const float* __restrict__ B,
    const float* __restrict__ bias, float* __restrict__ C, int O_total) {
    constexpr int TN = 128, KC = 16, PAD = 4;
    constexpr int TO = TILE_O / 16;
    __shared__ float sA[KC][TN + PAD];
    __shared__ float sB[KC][TILE_O + PAD];
    int tid = threadIdx.x;
    int n0 = blockIdx.x * TN;
    int o0 = blockIdx.y * TILE_O;
    int nsub = tid >> 4, osub = tid & 15;
    float acc[8][TO];
    #pragma unroll
    for (int i = 0; i < 8; i++)
        #pragma unroll
        for (int j = 0; j < TO; j++) acc[i][j] = 0.f;

    float breg[TO];
    #pragma unroll
    for (int j = 0; j < TO; j++) breg[j] = bias[o0 + osub*TO + j];

    for (int k0 = 0; k0 < K; k0 += KC) {
        __syncthreads();
        {
            int n_l = tid >> 1, k_l = (tid & 1) * 8;
            const float4* p = (const float4*)(A + (size_t)(n0 + n_l) * K + k0 + k_l);
            float4 v0 = p[0], v1 = p[1];
            sA[k_l+0][n_l] = v0.x; sA[k_l+1][n_l] = v0.y;
            sA[k_l+2][n_l] = v0.z; sA[k_l+3][n_l] = v0.w;
            sA[k_l+4][n_l] = v1.x; sA[k_l+5][n_l] = v1.y;
            sA[k_l+6][n_l] = v1.z; sA[k_l+7][n_l] = v1.w;
        }
        if constexpr (TILE_O == 128) {
            int o_l = tid >> 1, k_l = (tid & 1) * 8;
            const float4* p = (const float4*)(B + (size_t)(o0 + o_l) * K + k0 + k_l);
            float4 v0 = p[0], v1 = p[1];
            sB[k_l+0][o_l] = v0.x; sB[k_l+1][o_l] = v0.y;
            sB[k_l+2][o_l] = v0.z; sB[k_l+3][o_l] = v0.w;
            sB[k_l+4][o_l] = v1.x; sB[k_l+5][o_l] = v1.y;
            sB[k_l+6][o_l] = v1.z; sB[k_l+7][o_l] = v1.w;
        } else {
            int o_l = tid >> 2, k_l = (tid & 3) * 4;
            float4 v = *(const float4*)(B + (size_t)(o0 + o_l) * K + k0 + k_l);
            sB[k_l+0][o_l] = v.x; sB[k_l+1][o_l] = v.y;
            sB[k_l+2][o_l] = v.z; sB[k_l+3][o_l] = v.w;
        }
        __syncthreads();
        #pragma unroll
        for (int kk = 0; kk < KC; kk++) {
            float4 a0 = *(const float4*)&sA[kk][nsub*8];
            float4 a1 = *(const float4*)&sA[kk][nsub*8+4];
            float af[8] = {a0.x,a0.y,a0.z,a0.w,a1.x,a1.y,a1.z,a1.w};
            float bf[TO];
            if constexpr (TO == 8) {
                float4 b0 = *(const float4*)&sB[kk][osub*8];
                float4 b1 = *(const float4*)&sB[kk][osub*8+4];
                bf[0]=b0.x; bf[1]=b0.y; bf[2]=b0.z; bf[3]=b0.w;
                bf[4]=b1.x; bf[5]=b1.y; bf[6]=b1.z; bf[7]=b1.w;
            } else {
                float4 b0 = *(const float4*)&sB[kk][osub*4];
                bf[0]=b0.x; bf[1]=b0.y; bf[2]=b0.z; bf[3]=b0.w;
            }
            #pragma unroll
            for (int i = 0; i < 8; i++)
                #pragma unroll
                for (int j = 0; j < TO; j++)
                    acc[i][j] = fmaf(af[i], bf[j], acc[i][j]);
        }
    }
    #pragma unroll
    for (int i = 0; i < 8; i++) {
        size_t base = (size_t)(n0 + nsub*8 + i) * O_total + o0 + osub*TO;
        #pragma unroll
        for (int j = 0; j < TO; j += 4) {
            float4 v;
            v.x = fmaxf(acc[i][j+0] + breg[j+0], 0.f);
            v.y = fmaxf(acc[i][j+1] + breg[j+1], 0.f);
            v.z = fmaxf(acc[i][j+2] + breg[j+2], 0.f);
            v.w = fmaxf(acc[i][j+3] + breg[j+3], 0.f);
            *(float4*)(C + base + j) = v;
        }
    }
}

// -------- K: big GEMM via mma.sync bf16x3 + fused per-batch max ------------
// D[n,o] = sum_k A[n,k]*W[o,k], A=Ah+Al, W=Wh+Wl (bf16 splits);
// D ~= Ah*Wh + Ah*Wl + Al*Wh accumulated in fp32 (err ~2^-18 rel).
// CTA: 128 points x 128 outputs, K=128 resident. 8 warps, each 64x32.
// smem pitch 136 bf16 => all fragment LDS.32 bank-conflict-free.
#define GPITCH 136
#define GT_BYTES (128*GPITCH*2)          // 34816 per tile
#define GS_AH 0
#define GS_AL (GT_BYTES)
#define GS_WH (2*GT_BYTES)
#define GS_WL (3*GT_BYTES)
#define GS_RED (4*GT_BYTES)              // float[128*16] = 8192
#define GS_TOTAL (4*GT_BYTES + 128*16*4) // 147456

#define MMA_BF16(D, A, B) \
    asm("mma.sync.aligned.m16n8k16.row.col.f32.bf16.bf16.f32 " \
        "{%0,%1,%2,%3}, {%4,%5,%6,%7}, {%8,%9}, {%0,%1,%2,%3};" \
        : "+f"((D)[0]), "+f"((D)[1]), "+f"((D)[2]), "+f"((D)[3]) \
        : "r"((A)[0]), "r"((A)[1]), "r"((A)[2]), "r"((A)[3]), \
          "r"((B)[0]), "r"((B)[1]))

__global__ __launch_bounds__(256) void gemm_max_mma_kernel() {
    extern __shared__ __align__(16) char smem_g[];
    __nv_bfloat16* sAh = (__nv_bfloat16*)(smem_g + GS_AH);
    __nv_bfloat16* sAl = (__nv_bfloat16*)(smem_g + GS_AL);
    __nv_bfloat16* sWh = (__nv_bfloat16*)(smem_g + GS_WH);
    __nv_bfloat16* sWl = (__nv_bfloat16*)(smem_g + GS_WL);
    float* red = (float*)(smem_g + GS_RED);

    int tid = threadIdx.x;
    int b = blockIdx.x >> 4;
    int gm0 = (b << 11) + (blockIdx.x & 15) * 128;   // global point row
    int o0 = blockIdx.y * 128;                        // global output row

    // stage all four tiles (global rows are 128 bf16 = 256B, uint4 copies)
    for (int idx = tid; idx < 128*16; idx += 256) {
        int row = idx >> 4, seg = (idx & 15) * 8;
        *(uint4*)(sAh + row*GPITCH + seg) = *(const uint4*)(g_p128h + (size_t)(gm0+row)*128 + seg);
        *(uint4*)(sAl + row*GPITCH + seg) = *(const uint4*)(g_p128l + (size_t)(gm0+row)*128 + seg);
        *(uint4*)(sWh + row*GPITCH + seg) = *(const uint4*)(g_Wp2h + (size_t)(o0+row)*128 + seg);
        *(uint4*)(sWl + row*GPITCH + seg) = *(const uint4*)(g_Wp2l + (size_t)(o0+row)*128 + seg);
    }
    __syncthreads();

    int lane = tid & 31, w = tid >> 5;
    int g = lane >> 2, t = lane & 3;
    int mw64 = (w >> 2) * 64, nw32 = (w & 3) * 32;

    float acc[4][4][4];
    #pragma unroll
    for (int mt = 0; mt < 4; mt++)
        #pragma unroll
        for (int nt = 0; nt < 4; nt++)
            #pragma unroll
            for (int r = 0; r < 4; r++) acc[mt][nt][r] = 0.f;

    unsigned af[4][4], bfr[4][2];

    #pragma unroll 1
    for (int kc = 0; kc < 8; kc++) {
        int kb = kc * 16 + 2 * t;
        // A-hi fragments
        #pragma unroll
        for (int mt = 0; mt < 4; mt++) {
            int r0 = mw64 + mt*16 + g, r1 = r0 + 8;
            af[mt][0] = *(const unsigned*)(sAh + r0*GPITCH + kb);
            af[mt][1] = *(const unsigned*)(sAh + r1*GPITCH + kb);
            af[mt][2] = *(const unsigned*)(sAh + r0*GPITCH + kb + 8);
            af[mt][3] = *(const unsigned*)(sAh + r1*GPITCH + kb + 8);
        }
        // W-hi
        #pragma unroll
        for (int nt = 0; nt < 4; nt++) {
            int rn = nw32 + nt*8 + g;
            bfr[nt][0] = *(const unsigned*)(sWh + rn*GPITCH + kb);
            bfr[nt][1] = *(const unsigned*)(sWh + rn*GPITCH + kb + 8);
        }
        #pragma unroll
        for (int mt = 0; mt < 4; mt++)
            #pragma unroll
            for (int nt = 0; nt < 4; nt++) MMA_BF16(acc[mt][nt], af[mt], bfr[nt]);
        // W-lo (A still hi)
        #pragma unroll
        for (int nt = 0; nt < 4; nt++) {
            int rn = nw32 + nt*8 + g;
            bfr[nt][0] = *(const unsigned*)(sWl + rn*GPITCH + kb);
            bfr[nt][1] = *(const unsigned*)(sWl + rn*GPITCH + kb + 8);
        }
        #pragma unroll
        for (int mt = 0; mt < 4; mt++)
            #pragma unroll
            for (int nt = 0; nt < 4; nt++) MMA_BF16(acc[mt][nt], af[mt], bfr[nt]);
        // A-lo x W-hi
        #pragma unroll
        for (int mt = 0; mt < 4; mt++) {
            int r0 = mw64 + mt*16 + g, r1 = r0 + 8;
            af[mt][0] = *(const unsigned*)(sAl + r0*GPITCH + kb);
            af[mt][1] = *(const unsigned*)(sAl + r1*GPITCH + kb);
            af[mt][2] = *(const unsigned*)(sAl + r0*GPITCH + kb + 8);
            af[mt][3] = *(const unsigned*)(sAl + r1*GPITCH + kb + 8);
        }
        #pragma unroll
        for (int nt = 0; nt < 4; nt++) {
            int rn = nw32 + nt*8 + g;
            bfr[nt][0] = *(const unsigned*)(sWh + rn*GPITCH + kb);
            bfr[nt][1] = *(const unsigned*)(sWh + rn*GPITCH + kb + 8);
        }
        #pragma unroll
        for (int mt = 0; mt < 4; mt++)
            #pragma unroll
            for (int nt = 0; nt < 4; nt++) MMA_BF16(acc[mt][nt], af[mt], bfr[nt]);
    }

    // epilogue: max over this thread's 8 rows per column, then cross-thread
    // D frag layout: d0=D[g][2t], d1=D[g][2t+1], d2=D[g+8][2t], d3=D[g+8][2t+1]
    int slot = (w >> 2) * 8 + g;
    #pragma unroll
    for (int nt = 0; nt < 4; nt++) {
        float v0 = neg_inf(), v1 = neg_inf();
        #pragma unroll
        for (int mt = 0; mt < 4; mt++) {
            v0 = fmaxf(v0, fmaxf(acc[mt][nt][0], acc[mt][nt][2]));
            v1 = fmaxf(v1, fmaxf(acc[mt][nt][1], acc[mt][nt][3]));
        }
        int col = nw32 + nt*8 + 2*t;
        red[col * 16 + slot]       = v0;
        red[(col + 1) * 16 + slot] = v1;
    }
    __syncthreads();
    if (tid < 128) {
        float m = red[tid * 16];
        #pragma unroll
        for (int s = 1; s < 16; s++) m = fmaxf(m, red[tid * 16 + s]);
        atomicMax(&g_gmax[b * 1024 + o0 + tid], fenc(m));
    }
}

// ----------------------------- K: pool 64 ----------------------------------
__global__ __launch_bounds__(256) void pool64_kernel() {
    int tid = threadIdx.x, w = tid >> 5, lane = tid & 31;
    int gid = blockIdx.x * 8 + w;
    int boff = (gid >> 11) << 11;
    const int* id = g_idx + (size_t)gid * KNN;
    int myid = (lane < KNN) ? id[lane] : 0;
    float m0 = neg_inf(), m1 = neg_inf();
    #pragma unroll
    for (int j = 0; j < KNN; j++) {
        int nb = __shfl_sync(0xffffffffu, myid, j);
        const float* f = g_h64a + (size_t)(boff + nb) * 64;
        m0 = fmaxf(m0, f[lane]);
        m1 = fmaxf(m1, f[lane + 32]);
    }
    g_pool64[(size_t)gid*64 + lane]      = m0;
    g_pool64[(size_t)gid*64 + lane + 32] = m1;
}

// ------------- K: pool 128 -> bf16 hi/lo split (feeds mma gemm) ------------
__global__ __launch_bounds__(256) void pool128_kernel() {
    int tid = threadIdx.x, w = tid >> 5, lane = tid & 31;
    int gid = blockIdx.x * 8 + w;
    int boff = (gid >> 11) << 11;
    const int* id = g_idx + (size_t)gid * KNN;
    int myid = (lane < KNN) ? id[lane] : 0;
    float m0 = neg_inf(), m1 = neg_inf(), m2 = neg_inf(), m3 = neg_inf();
    #pragma unroll
    for (int j = 0; j < KNN; j++) {
        int nb = __shfl_sync(0xffffffffu, myid, j);
        const float* f = g_h128a + (size_t)(boff + nb) * 128;
        m0 = fmaxf(m0, f[lane]);
        m1 = fmaxf(m1, f[lane + 32]);
        m2 = fmaxf(m2, f[lane + 64]);
        m3 = fmaxf(m3, f[lane + 96]);
    }
    __nv_bfloat16* oh = g_p128h + (size_t)gid * 128;
    __nv_bfloat16* ol = g_p128l + (size_t)gid * 128;
    float vv[4] = {m0, m1, m2, m3};
    #pragma unroll
    for (int c = 0; c < 4; c++) {
        int col = lane + 32 * c;
        __nv_bfloat16 h = __float2bfloat16(vv[c]);
        oh[col] = h;
        ol[col] = __float2bfloat16(vv[c] - __bfloat162float(h));
    }
}

// ----------------------------- K: head MLP ---------------------------------
__global__ __launch_bounds__(512) void head_kernel(
    const float* __restrict__ W_m2a, const float* __restrict__ b_m2a,
    const float* __restrict__ W_m2b, const float* __restrict__ b_m2b,
    const float* __restrict__ W_emb, float* __restrict__ out) {
    __shared__ float sv[1024], sh1[512], sh2[512];
    int b = blockIdx.x, tid = threadIdx.x, w = tid >> 5, lane = tid & 31;
    sv[tid]       = fdec(g_gmax[b*1024 + tid])       + g_bp2[tid];
    sv[tid + 512] = fdec(g_gmax[b*1024 + tid + 512]) + g_bp2[tid + 512];
    __syncthreads();
    for (int r = 0; r < 32; r++) {
        int o = w * 32 + r;
        const float* Wr = W_m2a + (size_t)o * 1024;
        float acc = 0.f;
        #pragma unroll 8
        for (int i = 0; i < 32; i++) acc = fmaf(Wr[lane + 32*i], sv[lane + 32*i], acc);
        #pragma unroll
        for (int s = 16; s > 0; s >>= 1) acc += __shfl_xor_sync(0xffffffffu, acc, s);
        if (lane == 0) sh1[o] = fmaxf(acc + b_m2a[o], 0.f);
    }
    __syncthreads();
    for (int r = 0; r < 32; r++) {
        int o = w * 32 + r;
        const float* Wr = W_m2b + (size_t)o * 512;
        float acc = 0.f;
        #pragma unroll 8
        for (int i = 0; i < 16; i++) acc = fmaf(Wr[lane + 32*i], sh1[lane + 32*i], acc);
        #pragma unroll
        for (int s = 16; s > 0; s >>= 1) acc += __shfl_xor_sync(0xffffffffu, acc, s);
        if (lane == 0) sh2[o] = acc + b_m2b[o];
    }
    __syncthreads();
    for (int r = 0; r < 8; r++) {
        int j = w * 8 + r;
        const float* Wr = W_emb + (size_t)j * 512;
        float acc = 0.f;
        #pragma unroll 8
        for (int i = 0; i < 16; i++) acc = fmaf(Wr[lane + 32*i], sh2[lane + 32*i], acc);
        #pragma unroll
        for (int s = 16; s > 0; s >>= 1) acc += __shfl_xor_sync(0xffffffffu, acc, s);
        if (lane == 0) out[b*128 + j] = acc;
    }
}

// ----------------------------- launch --------------------------------------
extern "C" void kernel_launch(void* const* d_in, const int* in_sizes, int n_in,
                              void* d_out, int out_size) {
    const float* pts    = (const float*)d_in[0];
    const float* W_m1a  = (const float*)d_in[1];
    const float* b_m1a  = (const float*)d_in[2];
    const float* W_m1b  = (const float*)d_in[3];
    const float* b_m1b  = (const float*)d_in[4];
    const float* W_m1c  = (const float*)d_in[5];
    const float* b_m1c  = (const float*)d_in[6];
    const float* W_lin1 = (const float*)d_in[7];
    const float* b_lin1 = (const float*)d_in[8];
    const float* W_c1   = (const float*)d_in[9];
    const float* b_c1   = (const float*)d_in[10];
    const float* W_lin2 = (const float*)d_in[11];
    const float* b_lin2 = (const float*)d_in[12];
    const float* W_c2   = (const float*)d_in[13];
    const float* b_c2   = (const float*)d_in[14];
    const float* W_m2a  = (const float*)d_in[15];
    const float* b_m2a  = (const float*)d_in[16];
    const float* W_m2b  = (const float*)d_in[17];
    const float* b_m2b  = (const float*)d_in[18];
    const float* W_emb  = (const float*)d_in[19];
    float* out = (float*)d_out;

    static int smem_set = 0;
    if (!smem_set) {
        cudaFuncSetAttribute(gemm_max_mma_kernel,
                             cudaFuncAttributeMaxDynamicSharedMemorySize, GS_TOTAL);
        smem_set = 1;
    }

    float* t64a; cudaGetSymbolAddress((void**)&t64a, g_t64a);
    float* t64b; cudaGetSymbolAddress((void**)&t64b, g_t64b);
    float* h64a; cudaGetSymbolAddress((void**)&h64a, g_h64a);
    float* p64;  cudaGetSymbolAddress((void**)&p64,  g_pool64);
    float* h128; cudaGetSymbolAddress((void**)&h128, g_h128a);
    float* wp1;  cudaGetSymbolAddress((void**)&wp1,  g_Wp1);
    float* bp1;  cudaGetSymbolAddress((void**)&bp1,  g_bp1);

    zero_gmax_kernel<<<BATCH, 1024>>>();
    prep_wp1_kernel<<<32, 256>>>(W_c1, W_lin1, b_lin1, b_c1);
    prep_wp2_kernel<<<1024, 128>>>(W_c2, W_lin2, b_lin2, b_c2);

    knn_kernel<<<dim3(NPTS/256, BATCH), 256>>>(pts);
    cov_l1_kernel<<<NPT/8, 256>>>(pts, W_m1a, b_m1a);

    gemm_bias_relu_kernel<64, 64><<<dim3(NPT/128, 1), 256>>>(t64a, W_m1b, b_m1b, t64b, 64);
    gemm_bias_relu_kernel<64, 64><<<dim3(NPT/128, 1), 256>>>(t64b, W_m1c, b_m1c, h64a, 64);

    pool64_kernel<<<NPT/8, 256>>>();
    gemm_bias_relu_kernel<64, 128><<<dim3(NPT/128, 1), 256>>>(p64, wp1, bp1, h128, 128);

    pool128_kernel<<<NPT/8, 256>>>();
    gemm_max_mma_kernel<<<dim3(256, 8), 256, GS_TOTAL>>>();

    head_kernel<<<BATCH, 512>>>(W_m2a, b_m2a, W_m2b, b_m2b, W_emb, out);
}

// round 14
// speedup vs baseline: 8.4922x; 1.2417x over previous
#include <cuda_runtime.h>
#include <cuda_bf16.h>
#include <cstdint>

#define BATCH 16
#define NPTS  2048
#define KNN   16
#define NPT   (BATCH*NPTS)

// ----------------------------- scratch ------------------------------------
__device__ __align__(16) int      g_idx[NPT*KNN];
__device__ __align__(16) float    g_t64a[NPT*64];
__device__ __align__(16) float    g_t64b[NPT*64];
__device__ __align__(16) float    g_h64a[NPT*64];
__device__ __align__(16) float    g_pool64[NPT*64];
__device__ __align__(16) float    g_h128a[NPT*128];
__device__ __align__(16) float    g_Wp1[128*64];   // (Wc1@Wlin1)[o][c]
__device__ __align__(16) float    g_bp1[128];
__device__ __align__(16) float    g_bp2[1024];
__device__ __align__(16) unsigned g_gmax[BATCH*1024];
// bf16 hi/lo splits feeding the tensor-core gemm_max
__device__ __align__(16) __nv_bfloat16 g_p128h[NPT*128];
__device__ __align__(16) __nv_bfloat16 g_p128l[NPT*128];
__device__ __align__(16) __nv_bfloat16 g_Wp2h[1024*128];
__device__ __align__(16) __nv_bfloat16 g_Wp2l[1024*128];

__device__ __forceinline__ unsigned fenc(float f) {
    unsigned b = __float_as_uint(f);
    return (b & 0x80000000u) ? ~b : (b | 0x80000000u);
}
__device__ __forceinline__ float fdec(unsigned u) {
    return __uint_as_float((u & 0x80000000u) ? (u ^ 0x80000000u) : ~u);
}
__device__ __forceinline__ float neg_inf() { return __uint_as_float(0xff800000u); }

// ----------------------------- K: zero gmax --------------------------------
__global__ void zero_gmax_kernel() {
    g_gmax[blockIdx.x * 1024 + threadIdx.x] = 0u;
}

// ------------------- K: precompute W' = Wc1 @ Wlin1 ------------------------
__global__ __launch_bounds__(256) void prep_wp1_kernel(
    const float* __restrict__ Wc1, const float* __restrict__ Wlin1,
    const float* __restrict__ b_lin1, const float* __restrict__ b_c1) {
    int g = blockIdx.x * 256 + threadIdx.x;          // 8192
    int o = g >> 6, c = g & 63;
    float acc = 0.f;
    for (int m = 0; m < 64; m++) acc = fmaf(Wc1[o*64+m], Wlin1[m*64+c], acc);
    g_Wp1[o*64 + c] = acc;
    if (c == 0) {
        float bb = b_c1[o];
        for (int m = 0; m < 64; m++) bb = fmaf(Wc1[o*64+m], b_lin1[m], bb);
        g_bp1[o] = bb;
    }
}

// --------- K: precompute W'' = Wc2 @ Wlin2, emit bf16 hi/lo split ----------
__global__ __launch_bounds__(128) void prep_wp2_kernel(
    const float* __restrict__ Wc2, const float* __restrict__ Wlin2,
    const float* __restrict__ b_lin2, const float* __restrict__ b_c2) {
    int o = blockIdx.x, c = threadIdx.x;
    float acc = 0.f;
    for (int m = 0; m < 128; m++) acc = fmaf(Wc2[o*128+m], Wlin2[m*128+c], acc);
    __nv_bfloat16 h = __float2bfloat16(acc);
    g_Wp2h[o*128 + c] = h;
    g_Wp2l[o*128 + c] = __float2bfloat16(acc - __bfloat162float(h));
    if (c == 0) {
        float bb = b_c2[o];
        for (int m = 0; m < 128; m++) bb = fmaf(Wc2[o*128+m], b_lin2[m], bb);
        g_bp2[o] = bb;
    }
}

// ----------------------------- K: kNN ---------------------------------------
// One thread per query. Rank by r = q.x*x + q.y*y + q.z*z - 0.5*|p|^2
// (d = 2r - qxx monotone in r per query -> identical top-k set/order).
// Top-16 unsorted; threshold curmin kept eagerly. Insert locates the min slot
// by EQUALITY with curmin (values unique w.h.p.; list prefilled with first 16
// candidates so no duplicated -inf) -> insert path is ~63 branchless instr
// (was ~110 with the argmin scan).
__global__ __launch_bounds__(256) void knn_kernel(const float* __restrict__ pts) {
    __shared__ __align__(16) float2 sxy[NPTS];
    __shared__ __align__(16) float2 szh[NPTS];
    int b = blockIdx.y;
    const float* p = pts + (size_t)b * NPTS * 3;
    for (int i = threadIdx.x; i < NPTS; i += 256) {
        float x = p[i*3+0], y = p[i*3+1], z = p[i*3+2];
        float h = -0.5f * fmaf(z, z, fmaf(y, y, x * x));
        sxy[i] = make_float2(x, y);
        szh[i] = make_float2(z, h);
    }
    __syncthreads();
    int q = blockIdx.x * 256 + threadIdx.x;
    float2 qxy = sxy[q];
    float qx = qxy.x, qy = qxy.y, qz = szh[q].x;

    float vals[KNN]; int idxs[KNN];
    // prefill with candidates 0..15 (same semantics as inserting them)
    #pragma unroll
    for (int s = 0; s < KNN; s++) {
        float2 cxy = sxy[s], czh = szh[s];
        vals[s] = fmaf(qx, cxy.x, fmaf(qy, cxy.y, fmaf(qz, czh.x, czh.y)));
        idxs[s] = s;
    }
    float curmin = vals[0];
    #pragma unroll
    for (int s = 1; s < KNN; s++) curmin = fminf(curmin, vals[s]);

    for (int j = KNN; j < NPTS; j++) {
        float2 cxy = sxy[j], czh = szh[j];
        float r = fmaf(qx, cxy.x, fmaf(qy, cxy.y, fmaf(qz, czh.x, czh.y)));
        if (r > curmin) {
            // replace the min-valued slot (equality match, unique w.h.p.)
            #pragma unroll
            for (int s = 0; s < KNN; s++) {
                bool hit = (vals[s] == curmin);
                vals[s] = hit ? r : vals[s];
                idxs[s] = hit ? j : idxs[s];
            }
            // refresh threshold
            float nm = vals[0];
            #pragma unroll
            for (int s = 1; s < KNN; s++) nm = fminf(nm, vals[s]);
            curmin = nm;
        }
    }

    // emit sorted: value desc, tie -> smaller index (jax.lax.top_k order)
    int* o = g_idx + ((size_t)b * NPTS + q) * KNN;
    #pragma unroll
    for (int s = 0; s < KNN; s++) {
        float bv = vals[0]; int bi = idxs[0]; int bp = 0;
        #pragma unroll
        for (int t = 1; t < KNN; t++) {
            bool better = (vals[t] > bv) || (vals[t] == bv && idxs[t] < bi);
            bv = better ? vals[t] : bv;
            bi = better ? idxs[t] : bi;
            bp = better ? t : bp;
        }
        o[s] = bi;
        #pragma unroll
        for (int t = 0; t < KNN; t++) {
            bool kill = (t == bp);
            vals[t] = kill ? neg_inf() : vals[t];
        }
    }
}

// --------------- K: local_cov + mlp1 layer a (12->64 relu) -----------------
__global__ __launch_bounds__(256) void cov_l1_kernel(
    const float* __restrict__ pts,
    const float* __restrict__ W1, const float* __restrict__ b1) {
    __shared__ float sW[12*64];
    __shared__ float sb[64];
    int tid = threadIdx.x;
    for (int i = tid; i < 64*12; i += 256) { int o = i / 12, c = i % 12; sW[c*64 + o] = W1[i]; }
    if (tid < 64) sb[tid] = b1[tid];
    __syncthreads();
    int w = tid >> 5, lane = tid & 31;
    int gid = blockIdx.x * 8 + w;
    int b = gid >> 11, n = gid & 2047;
    const float* p = pts + (size_t)b * NPTS * 3;
    const int* id = g_idx + (size_t)gid * KNN;
    int i0 = id[0], i1 = id[1];
    float f[12];
    f[0] = p[n*3+0]; f[1] = p[n*3+1]; f[2] = p[n*3+2];
    float a0 = p[i0*3+0], a1 = p[i0*3+1], a2 = p[i0*3+2];
    float c0 = p[i1*3+0], c1 = p[i1*3+1], c2 = p[i1*3+2];
    f[3] = a0*c0; f[4]  = a0*c1; f[5]  = a0*c2;
    f[6] = a1*c0; f[7]  = a1*c1; f[8]  = a1*c2;
    f[9] = a2*c0; f[10] = a2*c1; f[11] = a2*c2;
    float h0 = sb[lane], h1 = sb[lane+32];
    #pragma unroll
    for (int c = 0; c < 12; c++) {
        h0 = fmaf(sW[c*64 + lane],      f[c], h0);
        h1 = fmaf(sW[c*64 + lane + 32], f[c], h1);
    }
    g_t64a[(size_t)gid*64 + lane]      = fmaxf(h0, 0.f);
    g_t64a[(size_t)gid*64 + lane + 32] = fmaxf(h1, 0.f);
}

// ----------------- K: register-tiled GEMM + bias + relu --------------------
template<int K, int TILE_O>
__global__ __launch_bounds__(256) void gemm_bias_relu_kernel(
    const float* __restrict__ A, const float* __restrict__ B,
    const float* __restrict__ bias, float* __restrict__ C, int O_total) {
    constexpr int TN = 128, KC = 16, PAD = 4;
    constexpr int TO = TILE_O / 16;
    __shared__ float sA[KC][TN + PAD];
    __shared__ float sB[KC][TILE_O + PAD];
    int tid = threadIdx.x;
    int n0 = blockIdx.x * TN;
    int o0 = blockIdx.y * TILE_O;
    int nsub = tid >> 4, osub = tid & 15;
    float acc[8][TO];
    #pragma unroll
    for (int i = 0; i < 8; i++)
        #pragma unroll
        for (int j = 0; j < TO; j++) acc[i][j] = 0.f;

    float breg[TO];
    #pragma unroll
    for (int j = 0; j < TO; j++) breg[j] = bias[o0 + osub*TO + j];

    for (int k0 = 0; k0 < K; k0 += KC) {
        __syncthreads();
        {
            int n_l = tid >> 1, k_l = (tid & 1) * 8;
            const float4* p = (const float4*)(A + (size_t)(n0 + n_l) * K + k0 + k_l);
            float4 v0 = p[0], v1 = p[1];
            sA[k_l+0][n_l] = v0.x; sA[k_l+1][n_l] = v0.y;
            sA[k_l+2][n_l] = v0.z; sA[k_l+3][n_l] = v0.w;
            sA[k_l+4][n_l] = v1.x; sA[k_l+5][n_l] = v1.y;
            sA[k_l+6][n_l] = v1.z; sA[k_l+7][n_l] = v1.w;
        }
        if constexpr (TILE_O == 128) {
            int o_l = tid >> 1, k_l = (tid & 1) * 8;
            const float4* p = (const float4*)(B + (size_t)(o0 + o_l) * K + k0 + k_l);
            float4 v0 = p[0], v1 = p[1];
            sB[k_l+0][o_l] = v0.x; sB[k_l+1][o_l] = v0.y;
            sB[k_l+2][o_l] = v0.z; sB[k_l+3][o_l] = v0.w;
            sB[k_l+4][o_l] = v1.x; sB[k_l+5][o_l] = v1.y;
            sB[k_l+6][o_l] = v1.z; sB[k_l+7][o_l] = v1.w;
        } else {
            int o_l = tid >> 2, k_l = (tid & 3) * 4;
            float4 v = *(const float4*)(B + (size_t)(o0 + o_l) * K + k0 + k_l);
            sB[k_l+0][o_l] = v.x; sB[k_l+1][o_l] = v.y;
            sB[k_l+2][o_l] = v.z; sB[k_l+3][o_l] = v.w;
        }
        __syncthreads();
        #pragma unroll
        for (int kk = 0; kk < KC; kk++) {
            float4 a0 = *(const float4*)&sA[kk][nsub*8];
            float4 a1 = *(const float4*)&sA[kk][nsub*8+4];
            float af[8] = {a0.x,a0.y,a0.z,a0.w,a1.x,a1.y,a1.z,a1.w};
            float bf[TO];
            if constexpr (TO == 8) {
                float4 b0 = *(const float4*)&sB[kk][osub*8];
                float4 b1 = *(const float4*)&sB[kk][osub*8+4];
                bf[0]=b0.x; bf[1]=b0.y; bf[2]=b0.z; bf[3]=b0.w;
                bf[4]=b1.x; bf[5]=b1.y; bf[6]=b1.z; bf[7]=b1.w;
            } else {
                float4 b0 = *(const float4*)&sB[kk][osub*4];
                bf[0]=b0.x; bf[1]=b0.y; bf[2]=b0.z; bf[3]=b0.w;
            }
            #pragma unroll
            for (int i = 0; i < 8; i++)
                #pragma unroll
                for (int j = 0; j < TO; j++)
                    acc[i][j] = fmaf(af[i], bf[j], acc[i][j]);
        }
    }
    #pragma unroll
    for (int i = 0; i < 8; i++) {
        size_t base = (size_t)(n0 + nsub*8 + i) * O_total + o0 + osub*TO;
        #pragma unroll
        for (int j = 0; j < TO; j += 4) {
            float4 v;
            v.x = fmaxf(acc[i][j+0] + breg[j+0], 0.f);
            v.y = fmaxf(acc[i][j+1] + breg[j+1], 0.f);
            v.z = fmaxf(acc[i][j+2] + breg[j+2], 0.f);
            v.w = fmaxf(acc[i][j+3] + breg[j+3], 0.f);
            *(float4*)(C + base + j) = v;
        }
    }
}

// -------- K: big GEMM via mma.sync bf16x3 + fused per-batch max ------------
#define GPITCH 136
#define GT_BYTES (128*GPITCH*2)
#define GS_AH 0
#define GS_AL (GT_BYTES)
#define GS_WH (2*GT_BYTES)
#define GS_WL (3*GT_BYTES)
#define GS_RED (4*GT_BYTES)
#define GS_TOTAL (4*GT_BYTES + 128*16*4)

#define MMA_BF16(D, A, B) \
    asm("mma.sync.aligned.m16n8k16.row.col.f32.bf16.bf16.f32 " \
        "{%0,%1,%2,%3}, {%4,%5,%6,%7}, {%8,%9}, {%0,%1,%2,%3};" \
        : "+f"((D)[0]), "+f"((D)[1]), "+f"((D)[2]), "+f"((D)[3]) \
        : "r"((A)[0]), "r"((A)[1]), "r"((A)[2]), "r"((A)[3]), \
          "r"((B)[0]), "r"((B)[1]))

__global__ __launch_bounds__(256) void gemm_max_mma_kernel() {
    extern __shared__ __align__(16) char smem_g[];
    __nv_bfloat16* sAh = (__nv_bfloat16*)(smem_g + GS_AH);
    __nv_bfloat16* sAl = (__nv_bfloat16*)(smem_g + GS_AL);
    __nv_bfloat16* sWh = (__nv_bfloat16*)(smem_g + GS_WH);
    __nv_bfloat16* sWl = (__nv_bfloat16*)(smem_g + GS_WL);
    float* red = (float*)(smem_g + GS_RED);

    int tid = threadIdx.x;
    int b = blockIdx.x >> 4;
    int gm0 = (b << 11) + (blockIdx.x & 15) * 128;
    int o0 = blockIdx.y * 128;

    for (int idx = tid; idx < 128*16; idx += 256) {
        int row = idx >> 4, seg = (idx & 15) * 8;
        *(uint4*)(sAh + row*GPITCH + seg) = *(const uint4*)(g_p128h + (size_t)(gm0+row)*128 + seg);
        *(uint4*)(sAl + row*GPITCH + seg) = *(const uint4*)(g_p128l + (size_t)(gm0+row)*128 + seg);
        *(uint4*)(sWh + row*GPITCH + seg) = *(const uint4*)(g_Wp2h + (size_t)(o0+row)*128 + seg);
        *(uint4*)(sWl + row*GPITCH + seg) = *(const uint4*)(g_Wp2l + (size_t)(o0+row)*128 + seg);
    }
    __syncthreads();

    int lane = tid & 31, w = tid >> 5;
    int g = lane >> 2, t = lane & 3;
    int mw64 = (w >> 2) * 64, nw32 = (w & 3) * 32;

    float acc[4][4][4];
    #pragma unroll
    for (int mt = 0; mt < 4; mt++)
        #pragma unroll
        for (int nt = 0; nt < 4; nt++)
            #pragma unroll
            for (int r = 0; r < 4; r++) acc[mt][nt][r] = 0.f;

    unsigned af[4][4], bfr[4][2];

    #pragma unroll 1
    for (int kc = 0; kc < 8; kc++) {
        int kb = kc * 16 + 2 * t;
        #pragma unroll
        for (int mt = 0; mt < 4; mt++) {
            int r0 = mw64 + mt*16 + g, r1 = r0 + 8;
            af[mt][0] = *(const unsigned*)(sAh + r0*GPITCH + kb);
            af[mt][1] = *(const unsigned*)(sAh + r1*GPITCH + kb);
            af[mt][2] = *(const unsigned*)(sAh + r0*GPITCH + kb + 8);
            af[mt][3] = *(const unsigned*)(sAh + r1*GPITCH + kb + 8);
        }
        #pragma unroll
        for (int nt = 0; nt < 4; nt++) {
            int rn = nw32 + nt*8 + g;
            bfr[nt][0] = *(const unsigned*)(sWh + rn*GPITCH + kb);
            bfr[nt][1] = *(const unsigned*)(sWh + rn*GPITCH + kb + 8);
        }
        #pragma unroll
        for (int mt = 0; mt < 4; mt++)
            #pragma unroll
            for (int nt = 0; nt < 4; nt++) MMA_BF16(acc[mt][nt], af[mt], bfr[nt]);
        #pragma unroll
        for (int nt = 0; nt < 4; nt++) {
            int rn = nw32 + nt*8 + g;
            bfr[nt][0] = *(const unsigned*)(sWl + rn*GPITCH + kb);
            bfr[nt][1] = *(const unsigned*)(sWl + rn*GPITCH + kb + 8);
        }
        #pragma unroll
        for (int mt = 0; mt < 4; mt++)
            #pragma unroll
            for (int nt = 0; nt < 4; nt++) MMA_BF16(acc[mt][nt], af[mt], bfr[nt]);
        #pragma unroll
        for (int mt = 0; mt < 4; mt++) {
            int r0 = mw64 + mt*16 + g, r1 = r0 + 8;
            af[mt][0] = *(const unsigned*)(sAl + r0*GPITCH + kb);
            af[mt][1] = *(const unsigned*)(sAl + r1*GPITCH + kb);
            af[mt][2] = *(const unsigned*)(sAl + r0*GPITCH + kb + 8);
            af[mt][3] = *(const unsigned*)(sAl + r1*GPITCH + kb + 8);
        }
        #pragma unroll
        for (int nt = 0; nt < 4; nt++) {
            int rn = nw32 + nt*8 + g;
            bfr[nt][0] = *(const unsigned*)(sWh + rn*GPITCH + kb);
            bfr[nt][1] = *(const unsigned*)(sWh + rn*GPITCH + kb + 8);
        }
        #pragma unroll
        for (int mt = 0; mt < 4; mt++)
            #pragma unroll
            for (int nt = 0; nt < 4; nt++) MMA_BF16(acc[mt][nt], af[mt], bfr[nt]);
    }

    int slot = (w >> 2) * 8 + g;
    #pragma unroll
    for (int nt = 0; nt < 4; nt++) {
        float v0 = neg_inf(), v1 = neg_inf();
        #pragma unroll
        for (int mt = 0; mt < 4; mt++) {
            v0 = fmaxf(v0, fmaxf(acc[mt][nt][0], acc[mt][nt][2]));
            v1 = fmaxf(v1, fmaxf(acc[mt][nt][1], acc[mt][nt][3]));
        }
        int col = nw32 + nt*8 + 2*t;
        red[col * 16 + slot]       = v0;
        red[(col + 1) * 16 + slot] = v1;
    }
    __syncthreads();
    if (tid < 128) {
        float m = red[tid * 16];
        #pragma unroll
        for (int s = 1; s < 16; s++) m = fmaxf(m, red[tid * 16 + s]);
        atomicMax(&g_gmax[b * 1024 + o0 + tid], fenc(m));
    }
}

// ----------------------------- K: pool 64 ----------------------------------
__global__ __launch_bounds__(256) void pool64_kernel() {
    int tid = threadIdx.x, w = tid >> 5, lane = tid & 31;
    int gid = blockIdx.x * 8 + w;
    int boff = (gid >> 11) << 11;
    const int* id = g_idx + (size_t)gid * KNN;
    int myid = (lane < KNN) ? id[lane] : 0;
    float m0 = neg_inf(), m1 = neg_inf();
    #pragma unroll
    for (int j = 0; j < KNN; j++) {
        int nb = __shfl_sync(0xffffffffu, myid, j);
        const float* f = g_h64a + (size_t)(boff + nb) * 64;
        m0 = fmaxf(m0, f[lane]);
        m1 = fmaxf(m1, f[lane + 32]);
    }
    g_pool64[(size_t)gid*64 + lane]      = m0;
    g_pool64[(size_t)gid*64 + lane + 32] = m1;
}

// ------------- K: pool 128 -> bf16 hi/lo split (feeds mma gemm) ------------
__global__ __launch_bounds__(256) void pool128_kernel() {
    int tid = threadIdx.x, w = tid >> 5, lane = tid & 31;
    int gid = blockIdx.x * 8 + w;
    int boff = (gid >> 11) << 11;
    const int* id = g_idx + (size_t)gid * KNN;
    int myid = (lane < KNN) ? id[lane] : 0;
    float m0 = neg_inf(), m1 = neg_inf(), m2 = neg_inf(), m3 = neg_inf();
    #pragma unroll
    for (int j = 0; j < KNN; j++) {
        int nb = __shfl_sync(0xffffffffu, myid, j);
        const float* f = g_h128a + (size_t)(boff + nb) * 128;
        m0 = fmaxf(m0, f[lane]);
        m1 = fmaxf(m1, f[lane + 32]);
        m2 = fmaxf(m2, f[lane + 64]);
        m3 = fmaxf(m3, f[lane + 96]);
    }
    __nv_bfloat16* oh = g_p128h + (size_t)gid * 128;
    __nv_bfloat16* ol = g_p128l + (size_t)gid * 128;
    float vv[4] = {m0, m1, m2, m3};
    #pragma unroll
    for (int c = 0; c < 4; c++) {
        int col = lane + 32 * c;
        __nv_bfloat16 h = __float2bfloat16(vv[c]);
        oh[col] = h;
        ol[col] = __float2bfloat16(vv[c] - __bfloat162float(h));
    }
}

// ----------------------------- K: head MLP ---------------------------------
__global__ __launch_bounds__(512) void head_kernel(
    const float* __restrict__ W_m2a, const float* __restrict__ b_m2a,
    const float* __restrict__ W_m2b, const float* __restrict__ b_m2b,
    const float* __restrict__ W_emb, float* __restrict__ out) {
    __shared__ float sv[1024], sh1[512], sh2[512];
    int b = blockIdx.x, tid = threadIdx.x, w = tid >> 5, lane = tid & 31;
    sv[tid]       = fdec(g_gmax[b*1024 + tid])       + g_bp2[tid];
    sv[tid + 512] = fdec(g_gmax[b*1024 + tid + 512]) + g_bp2[tid + 512];
    __syncthreads();
    for (int r = 0; r < 32; r++) {
        int o = w * 32 + r;
        const float* Wr = W_m2a + (size_t)o * 1024;
        float acc = 0.f;
        #pragma unroll 8
        for (int i = 0; i < 32; i++) acc = fmaf(Wr[lane + 32*i], sv[lane + 32*i], acc);
        #pragma unroll
        for (int s = 16; s > 0; s >>= 1) acc += __shfl_xor_sync(0xffffffffu, acc, s);
        if (lane == 0) sh1[o] = fmaxf(acc + b_m2a[o], 0.f);
    }
    __syncthreads();
    for (int r = 0; r < 32; r++) {
        int o = w * 32 + r;
        const float* Wr = W_m2b + (size_t)o * 512;
        float acc = 0.f;
        #pragma unroll 8
        for (int i = 0; i < 16; i++) acc = fmaf(Wr[lane + 32*i], sh1[lane + 32*i], acc);
        #pragma unroll
        for (int s = 16; s > 0; s >>= 1) acc += __shfl_xor_sync(0xffffffffu, acc, s);
        if (lane == 0) sh2[o] = acc + b_m2b[o];
    }
    __syncthreads();
    for (int r = 0; r < 8; r++) {
        int j = w * 8 + r;
        const float* Wr = W_emb + (size_t)j * 512;
        float acc = 0.f;
        #pragma unroll 8
        for (int i = 0; i < 16; i++) acc = fmaf(Wr[lane + 32*i], sh2[lane + 32*i], acc);
        #pragma unroll
        for (int s = 16; s > 0; s >>= 1) acc += __shfl_xor_sync(0xffffffffu, acc, s);
        if (lane == 0) out[b*128 + j] = acc;
    }
}

// ----------------------------- launch --------------------------------------
extern "C" void kernel_launch(void* const* d_in, const int* in_sizes, int n_in,
                              void* d_out, int out_size) {
    const float* pts    = (const float*)d_in[0];
    const float* W_m1a  = (const float*)d_in[1];
    const float* b_m1a  = (const float*)d_in[2];
    const float* W_m1b  = (const float*)d_in[3];
    const float* b_m1b  = (const float*)d_in[4];
    const float* W_m1c  = (const float*)d_in[5];
    const float* b_m1c  = (const float*)d_in[6];
    const float* W_lin1 = (const float*)d_in[7];
    const float* b_lin1 = (const float*)d_in[8];
    const float* W_c1   = (const float*)d_in[9];
    const float* b_c1   = (const float*)d_in[10];
    const float* W_lin2 = (const float*)d_in[11];
    const float* b_lin2 = (const float*)d_in[12];
    const float* W_c2   = (const float*)d_in[13];
    const float* b_c2   = (const float*)d_in[14];
    const float* W_m2a  = (const float*)d_in[15];
    const float* b_m2a  = (const float*)d_in[16];
    const float* W_m2b  = (const float*)d_in[17];
    const float* b_m2b  = (const float*)d_in[18];
    const float* W_emb  = (const float*)d_in[19];
    float* out = (float*)d_out;

    static int smem_set = 0;
    if (!smem_set) {
        cudaFuncSetAttribute(gemm_max_mma_kernel,
                             cudaFuncAttributeMaxDynamicSharedMemorySize, GS_TOTAL);
        smem_set = 1;
    }

    float* t64a; cudaGetSymbolAddress((void**)&t64a, g_t64a);
    float* t64b; cudaGetSymbolAddress((void**)&t64b, g_t64b);
    float* h64a; cudaGetSymbolAddress((void**)&h64a, g_h64a);
    float* p64;  cudaGetSymbolAddress((void**)&p64,  g_pool64);
    float* h128; cudaGetSymbolAddress((void**)&h128, g_h128a);
    float* wp1;  cudaGetSymbolAddress((void**)&wp1,  g_Wp1);
    float* bp1;  cudaGetSymbolAddress((void**)&bp1,  g_bp1);

    zero_gmax_kernel<<<BATCH, 1024>>>();
    prep_wp1_kernel<<<32, 256>>>(W_c1, W_lin1, b_lin1, b_c1);
    prep_wp2_kernel<<<1024, 128>>>(W_c2, W_lin2, b_lin2, b_c2);

    knn_kernel<<<dim3(NPTS/256, BATCH), 256>>>(pts);
    cov_l1_kernel<<<NPT/8, 256>>>(pts, W_m1a, b_m1a);

    gemm_bias_relu_kernel<64, 64><<<dim3(NPT/128, 1), 256>>>(t64a, W_m1b, b_m1b, t64b, 64);
    gemm_bias_relu_kernel<64, 64><<<dim3(NPT/128, 1), 256>>>(t64b, W_m1c, b_m1c, h64a, 64);

    pool64_kernel<<<NPT/8, 256>>>();
    gemm_bias_relu_kernel<64, 128><<<dim3(NPT/128, 1), 256>>>(p64, wp1, bp1, h128, 128);

    pool128_kernel<<<NPT/8, 256>>>();
    gemm_max_mma_kernel<<<dim3(256, 8), 256, GS_TOTAL>>>();

    head_kernel<<<BATCH, 512>>>(W_m2a, b_m2a, W_m2b, b_m2b, W_emb, out);
}